// round 1
// baseline (speedup 1.0000x reference)
#include <cuda_runtime.h>
#include <math.h>
#include <stdint.h>

// ---------------- problem constants ----------------
#define TOK    25088      // 8*56*56
#define NBATCH 8
#define HWDIM  56
#define CDIM   256
#define QKC    768        // qkv width
#define HIDC   1024
#define NWIN   49         // 7*7 windows per image
#define NPALL  392        // 8*49
#define WSCALE 0.0625f    // 256^-0.5

// ---------------- scratch (device globals; no allocs allowed) ----------------
__device__ float g_tmp256[TOK * CDIM];     // ln1(win-order) -> attn+lepe(img) -> ln2
__device__ float g_qkv[TOK * QKC];         // windowed token order
__device__ float g_x1[TOK * CDIM];         // after first residual
__device__ float g_hid[(size_t)TOK * HIDC];
__device__ float g_qwin[NPALL * CDIM];
__device__ float g_kwin[NPALL * CDIM];
__device__ int   g_topk[NPALL * 4];

// ---------------- LayerNorm (warp per token), optional window permute ----------------
template<bool PERM>
__global__ void ln_kernel(const float* __restrict__ X, const float* __restrict__ gam,
                          const float* __restrict__ bet, float* __restrict__ Y) {
    int warp = threadIdx.x >> 5, lane = threadIdx.x & 31;
    int t = blockIdx.x * 8 + warp;
    const float* row = X + (size_t)t * CDIM;
    float4 v0 = *(const float4*)(row + lane * 8);
    float4 v1 = *(const float4*)(row + lane * 8 + 4);
    float s  = v0.x + v0.y + v0.z + v0.w + v1.x + v1.y + v1.z + v1.w;
    float sq = v0.x*v0.x + v0.y*v0.y + v0.z*v0.z + v0.w*v0.w
             + v1.x*v1.x + v1.y*v1.y + v1.z*v1.z + v1.w*v1.w;
    #pragma unroll
    for (int o = 16; o; o >>= 1) {
        s  += __shfl_xor_sync(0xffffffffu, s, o);
        sq += __shfl_xor_sync(0xffffffffu, sq, o);
    }
    float mu  = s * (1.0f / 256.0f);
    float var = sq * (1.0f / 256.0f) - mu * mu;
    float inv = rsqrtf(var + 1e-6f);

    int orow;
    if (PERM) {
        int n = t / 3136, rem = t % 3136;
        int y = rem / 56, x = rem % 56;
        int p  = (y >> 3) * 7 + (x >> 3);
        int qi = (y & 7) * 8 + (x & 7);
        orow = (n * NWIN + p) * 64 + qi;
    } else {
        orow = t;
    }
    float4 g0 = *(const float4*)(gam + lane * 8);
    float4 g1 = *(const float4*)(gam + lane * 8 + 4);
    float4 b0 = *(const float4*)(bet + lane * 8);
    float4 b1 = *(const float4*)(bet + lane * 8 + 4);
    float4 o0, o1;
    o0.x = (v0.x - mu) * inv * g0.x + b0.x;
    o0.y = (v0.y - mu) * inv * g0.y + b0.y;
    o0.z = (v0.z - mu) * inv * g0.z + b0.z;
    o0.w = (v0.w - mu) * inv * g0.w + b0.w;
    o1.x = (v1.x - mu) * inv * g1.x + b1.x;
    o1.y = (v1.y - mu) * inv * g1.y + b1.y;
    o1.z = (v1.z - mu) * inv * g1.z + b1.z;
    o1.w = (v1.w - mu) * inv * g1.w + b1.w;
    float* orp = Y + (size_t)orow * CDIM + lane * 8;
    *(float4*)(orp)     = o0;
    *(float4*)(orp + 4) = o1;
}

// ---------------- SGEMM 128x128x8, 256 threads, 8x8 per thread ----------------
// EPI: 0 = bias only, 1 = bias + exact GELU, 2 = bias + residual add
__device__ __forceinline__ float gelu_exact(float x) {
    return 0.5f * x * (1.0f + erff(x * 0.70710678118654752440f));
}

template<int EPI>
__global__ void sgemm_kernel(const float* __restrict__ A, const float* __restrict__ B,
                             const float* __restrict__ bias, const float* __restrict__ R,
                             float* __restrict__ C, int M, int N, int K) {
    __shared__ float As[8][128];
    __shared__ float Bs[8][128];
    int tid = threadIdx.x;
    int m0 = blockIdx.y * 128, n0 = blockIdx.x * 128;
    int ty = tid >> 4, tx = tid & 15;
    int arow = tid >> 1, acol = (tid & 1) * 4;
    int brow = tid >> 5, bcol = (tid & 31) * 4;
    const float* Aptr = A + (size_t)(m0 + arow) * K + acol;
    const float* Bptr = B + (size_t)brow * N + n0 + bcol;

    float acc[8][8];
    #pragma unroll
    for (int i = 0; i < 8; i++)
        #pragma unroll
        for (int j = 0; j < 8; j++) acc[i][j] = 0.0f;

    for (int k0 = 0; k0 < K; k0 += 8) {
        float4 av = *(const float4*)(Aptr + k0);
        As[acol + 0][arow] = av.x;
        As[acol + 1][arow] = av.y;
        As[acol + 2][arow] = av.z;
        As[acol + 3][arow] = av.w;
        *(float4*)&Bs[brow][bcol] = *(const float4*)(Bptr + (size_t)k0 * N);
        __syncthreads();
        #pragma unroll
        for (int k = 0; k < 8; k++) {
            float a[8], b[8];
            *(float4*)(a)     = *(const float4*)&As[k][ty * 8];
            *(float4*)(a + 4) = *(const float4*)&As[k][ty * 8 + 4];
            *(float4*)(b)     = *(const float4*)&Bs[k][tx * 8];
            *(float4*)(b + 4) = *(const float4*)&Bs[k][tx * 8 + 4];
            #pragma unroll
            for (int i = 0; i < 8; i++)
                #pragma unroll
                for (int j = 0; j < 8; j++) acc[i][j] += a[i] * b[j];
        }
        __syncthreads();
    }

    float bv[8];
    #pragma unroll
    for (int j = 0; j < 8; j++) bv[j] = bias[n0 + tx * 8 + j];
    #pragma unroll
    for (int i = 0; i < 8; i++) {
        int row = m0 + ty * 8 + i;
        float* crow = C + (size_t)row * N + n0 + tx * 8;
        #pragma unroll
        for (int j0 = 0; j0 < 8; j0 += 4) {
            float v[4];
            #pragma unroll
            for (int j = 0; j < 4; j++) {
                float t = acc[i][j0 + j] + bv[j0 + j];
                if (EPI == 1) t = gelu_exact(t);
                v[j] = t;
            }
            if (EPI == 2) {
                const float* rrow = R + (size_t)row * N + n0 + tx * 8;
                float4 rv = *(const float4*)(rrow + j0);
                v[0] += rv.x; v[1] += rv.y; v[2] += rv.z; v[3] += rv.w;
            }
            float4 ov; ov.x = v[0]; ov.y = v[1]; ov.z = v[2]; ov.w = v[3];
            *(float4*)(crow + j0) = ov;
        }
    }
}

// ---------------- per-window mean of q and k ----------------
__global__ void winmean_kernel(const float* __restrict__ QKV,
                               float* __restrict__ qw, float* __restrict__ kw) {
    int np = blockIdx.x;           // 0..391
    int c = threadIdx.x;           // 0..255
    const float* base = QKV + (size_t)np * 64 * QKC;
    float sq = 0.f, sk = 0.f;
    #pragma unroll 8
    for (int t = 0; t < 64; t++) {
        sq += base[(size_t)t * QKC + c];
        sk += base[(size_t)t * QKC + 256 + c];
    }
    qw[np * CDIM + c] = sq * (1.0f / 64.0f);
    kw[np * CDIM + c] = sk * (1.0f / 64.0f);
}

// ---------------- router logits + top-4 ----------------
__global__ void router_kernel(const float* __restrict__ qw, const float* __restrict__ kw,
                              int* __restrict__ topk) {
    int np = blockIdx.x;
    int n = np / NWIN;
    int tid = threadIdx.x;         // 64 threads
    __shared__ float qs[CDIM];
    __shared__ float lg[NWIN];
    for (int i = tid; i < CDIM; i += 64) qs[i] = qw[np * CDIM + i] * WSCALE;
    __syncthreads();
    if (tid < NWIN) {
        const float* kr = kw + (size_t)(n * NWIN + tid) * CDIM;
        float s = 0.f;
        #pragma unroll 8
        for (int c = 0; c < CDIM; c++) s += qs[c] * kr[c];
        lg[tid] = s;
    }
    __syncthreads();
    if (tid == 0) {
        bool used[NWIN];
        #pragma unroll
        for (int i = 0; i < NWIN; i++) used[i] = false;
        for (int r = 0; r < 4; r++) {
            float best = -1e30f; int bi = 0;
            for (int q = 0; q < NWIN; q++)
                if (!used[q] && lg[q] > best) { best = lg[q]; bi = q; }
            used[bi] = true;
            topk[np * 4 + r] = bi;
        }
    }
}

// ---------------- gathered attention, online softmax ----------------
// grid (392, 8 heads), 64 threads = 64 queries
__global__ void attn_kernel(const float* __restrict__ QKV, const int* __restrict__ topk,
                            float* __restrict__ O) {
    __shared__ float ks[64][32];
    __shared__ float vs[64][32];
    int np = blockIdx.x, mh = blockIdx.y;
    int n = np / NWIN, p = np % NWIN;
    int tid = threadIdx.x;

    const float* qrow = QKV + ((size_t)np * 64 + tid) * QKC + mh * 32;
    float q[32];
    #pragma unroll
    for (int i = 0; i < 32; i += 4) {
        float4 v = *(const float4*)(qrow + i);
        q[i] = v.x * WSCALE; q[i + 1] = v.y * WSCALE;
        q[i + 2] = v.z * WSCALE; q[i + 3] = v.w * WSCALE;
    }

    float mrun = -1e30f, lrun = 0.f;
    float acc[32];
    #pragma unroll
    for (int c = 0; c < 32; c++) acc[c] = 0.f;

    for (int t4 = 0; t4 < 4; t4++) {
        int r = topk[np * 4 + t4];
        const float* kbase = QKV + (size_t)(n * NWIN + r) * 64 * QKC + 256 + mh * 32;
        // stage 64x32 K and V tiles
        for (int idx = tid; idx < 512; idx += 64) {
            int rr = idx >> 3, cc = (idx & 7) * 4;
            *(float4*)&ks[rr][cc] = *(const float4*)(kbase + (size_t)rr * QKC + cc);
            *(float4*)&vs[rr][cc] = *(const float4*)(kbase + (size_t)rr * QKC + 256 + cc);
        }
        __syncthreads();

        float s[64];
        float mc = mrun;
        #pragma unroll
        for (int j = 0; j < 64; j++) {
            float d = 0.f;
            #pragma unroll
            for (int c = 0; c < 32; c++) d += q[c] * ks[j][c];
            s[j] = d;
            mc = fmaxf(mc, d);
        }
        float corr = __expf(mrun - mc);
        lrun *= corr;
        #pragma unroll
        for (int c = 0; c < 32; c++) acc[c] *= corr;
        #pragma unroll
        for (int j = 0; j < 64; j++) {
            float pj = __expf(s[j] - mc);
            lrun += pj;
            #pragma unroll
            for (int c = 0; c < 32; c++) acc[c] += pj * vs[j][c];
        }
        mrun = mc;
        __syncthreads();
    }

    float inv = 1.0f / lrun;
    int jj = p / 7, ii = p % 7, hh = tid >> 3, ww = tid & 7;
    int y = jj * 8 + hh, xx = ii * 8 + ww;
    float* orow = O + ((size_t)(n * HWDIM + y) * HWDIM + xx) * CDIM + mh * 32;
    #pragma unroll
    for (int c = 0; c < 32; c += 4) {
        float4 v;
        v.x = acc[c] * inv; v.y = acc[c + 1] * inv;
        v.z = acc[c + 2] * inv; v.w = acc[c + 3] * inv;
        *(float4*)(orow + c) = v;
    }
}

// ---------------- 5x5 depthwise lepe, accumulates into attention output ----------------
__global__ void lepe_kernel(const float* __restrict__ QKV, const float* __restrict__ W,
                            const float* __restrict__ B, float* __restrict__ O) {
    int t = blockIdx.x;
    int c = threadIdx.x;
    int n = t / 3136, rem = t % 3136;
    int y = rem / 56, x = rem % 56;
    float acc = B[c];
    #pragma unroll
    for (int dy = -2; dy <= 2; dy++) {
        int yy = y + dy;
        if (yy < 0 || yy >= 56) continue;
        #pragma unroll
        for (int dx = -2; dx <= 2; dx++) {
            int xx = x + dx;
            if (xx < 0 || xx >= 56) continue;
            int p  = (yy >> 3) * 7 + (xx >> 3);
            int qi = (yy & 7) * 8 + (xx & 7);
            size_t rowi = ((size_t)(n * NWIN + p) * 64 + qi) * QKC + 512;
            acc += QKV[rowi + c] * W[((dy + 2) * 5 + (dx + 2)) * CDIM + c];
        }
    }
    O[(size_t)t * CDIM + c] += acc;
}

// ---------------- host launch ----------------
extern "C" void kernel_launch(void* const* d_in, const int* in_sizes, int n_in,
                              void* d_out, int out_size) {
    const float* x      = (const float*)d_in[0];
    const float* ln1_g  = (const float*)d_in[1];
    const float* ln1_b  = (const float*)d_in[2];
    const float* qkv_w  = (const float*)d_in[3];
    const float* qkv_b  = (const float*)d_in[4];
    const float* lepe_w = (const float*)d_in[5];
    const float* lepe_b = (const float*)d_in[6];
    const float* wo_w   = (const float*)d_in[7];
    const float* wo_b   = (const float*)d_in[8];
    const float* ln2_g  = (const float*)d_in[9];
    const float* ln2_b  = (const float*)d_in[10];
    const float* mlp_w1 = (const float*)d_in[11];
    const float* mlp_b1 = (const float*)d_in[12];
    const float* mlp_w2 = (const float*)d_in[13];
    const float* mlp_b2 = (const float*)d_in[14];
    float* out = (float*)d_out;

    float *tmp, *qkv, *x1, *hid, *qw, *kw;
    int* tk;
    cudaGetSymbolAddress((void**)&tmp, g_tmp256);
    cudaGetSymbolAddress((void**)&qkv, g_qkv);
    cudaGetSymbolAddress((void**)&x1,  g_x1);
    cudaGetSymbolAddress((void**)&hid, g_hid);
    cudaGetSymbolAddress((void**)&qw,  g_qwin);
    cudaGetSymbolAddress((void**)&kw,  g_kwin);
    cudaGetSymbolAddress((void**)&tk,  g_topk);

    // 1. LN1 with window permute (image -> windowed token order)
    ln_kernel<true><<<TOK / 8, 256>>>(x, ln1_g, ln1_b, tmp);
    // 2. qkv GEMM: [25088,256] x [256,768]
    sgemm_kernel<0><<<dim3(QKC / 128, TOK / 128), 256>>>(tmp, qkv_w, qkv_b, nullptr, qkv,
                                                         TOK, QKC, CDIM);
    // 3. window means
    winmean_kernel<<<NPALL, 256>>>(qkv, qw, kw);
    // 4. router + top-4
    router_kernel<<<NPALL, 64>>>(qw, kw, tk);
    // 5. gathered attention (writes image order into tmp)
    attn_kernel<<<dim3(NPALL, 8), 64>>>(qkv, tk, tmp);
    // 6. lepe depthwise conv accumulates into tmp
    lepe_kernel<<<TOK, 256>>>(qkv, lepe_w, lepe_b, tmp);
    // 7. wo GEMM + residual with original x -> x1
    sgemm_kernel<2><<<dim3(CDIM / 128, TOK / 128), 256>>>(tmp, wo_w, wo_b, x, x1,
                                                          TOK, CDIM, CDIM);
    // 8. LN2 (no permute)
    ln_kernel<false><<<TOK / 8, 256>>>(x1, ln2_g, ln2_b, tmp);
    // 9. MLP1 + exact GELU
    sgemm_kernel<1><<<dim3(HIDC / 128, TOK / 128), 256>>>(tmp, mlp_w1, mlp_b1, nullptr, hid,
                                                          TOK, HIDC, CDIM);
    // 10. MLP2 + residual -> out
    sgemm_kernel<2><<<dim3(CDIM / 128, TOK / 128), 256>>>(hid, mlp_w2, mlp_b2, x1, out,
                                                          TOK, CDIM, HIDC);
}

// round 2
// speedup vs baseline: 1.9025x; 1.9025x over previous
#include <cuda_runtime.h>
#include <math.h>
#include <stdint.h>

// ---------------- problem constants ----------------
#define TOK    25088      // 8*56*56
#define NBATCH 8
#define HWDIM  56
#define CDIM   256
#define QKC    768        // qkv width
#define HIDC   1024
#define NWIN   49         // 7*7 windows per image
#define NPALL  392        // 8*49
#define WSCALE 0.0625f    // 256^-0.5

// ---------------- scratch (device globals; no allocs allowed) ----------------
__device__ float g_tmp256[TOK * CDIM];     // ln1(win-order) -> attn+lepe(img) -> ln2
__device__ float g_qkv[TOK * QKC];         // windowed token order
__device__ float g_x1[TOK * CDIM];         // after first residual
__device__ float g_hid[(size_t)TOK * HIDC];
__device__ float g_qwin[NPALL * CDIM];
__device__ float g_kwin[NPALL * CDIM];
__device__ int   g_topk[NPALL * 4];

// ---------------- LayerNorm (warp per token), optional window permute ----------------
template<bool PERM>
__global__ void ln_kernel(const float* __restrict__ X, const float* __restrict__ gam,
                          const float* __restrict__ bet, float* __restrict__ Y) {
    int warp = threadIdx.x >> 5, lane = threadIdx.x & 31;
    int t = blockIdx.x * 8 + warp;
    const float* row = X + (size_t)t * CDIM;
    float4 v0 = *(const float4*)(row + lane * 8);
    float4 v1 = *(const float4*)(row + lane * 8 + 4);
    float s  = v0.x + v0.y + v0.z + v0.w + v1.x + v1.y + v1.z + v1.w;
    float sq = v0.x*v0.x + v0.y*v0.y + v0.z*v0.z + v0.w*v0.w
             + v1.x*v1.x + v1.y*v1.y + v1.z*v1.z + v1.w*v1.w;
    #pragma unroll
    for (int o = 16; o; o >>= 1) {
        s  += __shfl_xor_sync(0xffffffffu, s, o);
        sq += __shfl_xor_sync(0xffffffffu, sq, o);
    }
    float mu  = s * (1.0f / 256.0f);
    float var = sq * (1.0f / 256.0f) - mu * mu;
    float inv = rsqrtf(var + 1e-6f);

    int orow;
    if (PERM) {
        int n = t / 3136, rem = t % 3136;
        int y = rem / 56, x = rem % 56;
        int p  = (y >> 3) * 7 + (x >> 3);
        int qi = (y & 7) * 8 + (x & 7);
        orow = (n * NWIN + p) * 64 + qi;
    } else {
        orow = t;
    }
    float4 g0 = *(const float4*)(gam + lane * 8);
    float4 g1 = *(const float4*)(gam + lane * 8 + 4);
    float4 b0 = *(const float4*)(bet + lane * 8);
    float4 b1 = *(const float4*)(bet + lane * 8 + 4);
    float4 o0, o1;
    o0.x = (v0.x - mu) * inv * g0.x + b0.x;
    o0.y = (v0.y - mu) * inv * g0.y + b0.y;
    o0.z = (v0.z - mu) * inv * g0.z + b0.z;
    o0.w = (v0.w - mu) * inv * g0.w + b0.w;
    o1.x = (v1.x - mu) * inv * g1.x + b1.x;
    o1.y = (v1.y - mu) * inv * g1.y + b1.y;
    o1.z = (v1.z - mu) * inv * g1.z + b1.z;
    o1.w = (v1.w - mu) * inv * g1.w + b1.w;
    float* orp = Y + (size_t)orow * CDIM + lane * 8;
    *(float4*)(orp)     = o0;
    *(float4*)(orp + 4) = o1;
}

// ---------------- TF32 tensor-core GEMM 128x128x16, 256 threads ----------------
// 8 warps in 2(m) x 4(n); each warp: 64x32 = 4x4 tiles of m16n8k8.
// EPI: 0 = bias only, 1 = bias + exact GELU, 2 = bias + residual add
__device__ __forceinline__ float gelu_exact(float x) {
    return 0.5f * x * (1.0f + erff(x * 0.70710678118654752440f));
}

__device__ __forceinline__ uint32_t f2tf32(float x) {
    uint32_t u;
    asm("cvt.rna.tf32.f32 %0, %1;" : "=r"(u) : "f"(x));
    return u;
}

#define ASTRIDE 20
#define BSTRIDE 136

template<int EPI>
__global__ __launch_bounds__(256)
void tgemm_kernel(const float* __restrict__ A, const float* __restrict__ B,
                  const float* __restrict__ bias, const float* __restrict__ R,
                  float* __restrict__ C, int M, int N, int K) {
    __shared__ float sA[2][128 * ASTRIDE];   // [m][k], k-stride padded to 20
    __shared__ float sB[2][16 * BSTRIDE];    // [k][n], n-stride padded to 136

    int tid = threadIdx.x;
    int warp = tid >> 5, lane = tid & 31;
    int qr = lane >> 2, qc = lane & 3;
    int warp_m = warp >> 2, warp_n = warp & 3;   // 2 x 4
    int m0 = blockIdx.y * 128, n0 = blockIdx.x * 128;

    // global load assignments
    int aRow = tid >> 1, aCol = (tid & 1) * 8;   // 128 rows x 16 k
    int bRow = tid >> 4, bCol = (tid & 15) * 8;  // 16 k x 128 n
    const float* Ag = A + (size_t)(m0 + aRow) * K + aCol;
    const float* Bg = B + (size_t)bRow * N + n0 + bCol;

    float acc[4][4][4];
    #pragma unroll
    for (int i = 0; i < 4; i++)
        #pragma unroll
        for (int j = 0; j < 4; j++)
            #pragma unroll
            for (int v = 0; v < 4; v++) acc[i][j][v] = 0.0f;

    // prologue: load k-tile 0 into buffer 0
    {
        float4 a0 = *(const float4*)(Ag);
        float4 a1 = *(const float4*)(Ag + 4);
        float4 b0 = *(const float4*)(Bg);
        float4 b1 = *(const float4*)(Bg + 4);
        float* dstA = &sA[0][aRow * ASTRIDE + aCol];
        dstA[0] = __uint_as_float(f2tf32(a0.x)); dstA[1] = __uint_as_float(f2tf32(a0.y));
        dstA[2] = __uint_as_float(f2tf32(a0.z)); dstA[3] = __uint_as_float(f2tf32(a0.w));
        dstA[4] = __uint_as_float(f2tf32(a1.x)); dstA[5] = __uint_as_float(f2tf32(a1.y));
        dstA[6] = __uint_as_float(f2tf32(a1.z)); dstA[7] = __uint_as_float(f2tf32(a1.w));
        float* dstB = &sB[0][bRow * BSTRIDE + bCol];
        dstB[0] = __uint_as_float(f2tf32(b0.x)); dstB[1] = __uint_as_float(f2tf32(b0.y));
        dstB[2] = __uint_as_float(f2tf32(b0.z)); dstB[3] = __uint_as_float(f2tf32(b0.w));
        dstB[4] = __uint_as_float(f2tf32(b1.x)); dstB[5] = __uint_as_float(f2tf32(b1.y));
        dstB[6] = __uint_as_float(f2tf32(b1.z)); dstB[7] = __uint_as_float(f2tf32(b1.w));
    }
    __syncthreads();

    int p = 0;
    for (int k0 = 0; k0 < K; k0 += 16) {
        bool more = (k0 + 16) < K;
        float4 na0, na1, nb0, nb1;
        if (more) {
            na0 = *(const float4*)(Ag + k0 + 16);
            na1 = *(const float4*)(Ag + k0 + 20);
            nb0 = *(const float4*)(Bg + (size_t)(k0 + 16) * N);
            nb1 = *(const float4*)(Bg + (size_t)(k0 + 16) * N + 4);
        }

        const float* Ab = sA[p];
        const float* Bb = sB[p];
        #pragma unroll
        for (int ks = 0; ks < 16; ks += 8) {
            uint32_t af[4][4], bf[4][2];
            #pragma unroll
            for (int mt = 0; mt < 4; mt++) {
                int r = warp_m * 64 + mt * 16 + qr;
                af[mt][0] = __float_as_uint(Ab[(r)     * ASTRIDE + ks + qc]);
                af[mt][1] = __float_as_uint(Ab[(r + 8) * ASTRIDE + ks + qc]);
                af[mt][2] = __float_as_uint(Ab[(r)     * ASTRIDE + ks + qc + 4]);
                af[mt][3] = __float_as_uint(Ab[(r + 8) * ASTRIDE + ks + qc + 4]);
            }
            #pragma unroll
            for (int nt = 0; nt < 4; nt++) {
                int cn = warp_n * 32 + nt * 8 + qr;
                bf[nt][0] = __float_as_uint(Bb[(ks + qc)     * BSTRIDE + cn]);
                bf[nt][1] = __float_as_uint(Bb[(ks + qc + 4) * BSTRIDE + cn]);
            }
            #pragma unroll
            for (int mt = 0; mt < 4; mt++)
                #pragma unroll
                for (int nt = 0; nt < 4; nt++) {
                    asm volatile(
                        "mma.sync.aligned.m16n8k8.row.col.f32.tf32.tf32.f32 "
                        "{%0,%1,%2,%3}, {%4,%5,%6,%7}, {%8,%9}, {%0,%1,%2,%3};"
                        : "+f"(acc[mt][nt][0]), "+f"(acc[mt][nt][1]),
                          "+f"(acc[mt][nt][2]), "+f"(acc[mt][nt][3])
                        : "r"(af[mt][0]), "r"(af[mt][1]), "r"(af[mt][2]), "r"(af[mt][3]),
                          "r"(bf[nt][0]), "r"(bf[nt][1]));
                }
        }

        if (more) {
            float* dstA = &sA[p ^ 1][aRow * ASTRIDE + aCol];
            dstA[0] = __uint_as_float(f2tf32(na0.x)); dstA[1] = __uint_as_float(f2tf32(na0.y));
            dstA[2] = __uint_as_float(f2tf32(na0.z)); dstA[3] = __uint_as_float(f2tf32(na0.w));
            dstA[4] = __uint_as_float(f2tf32(na1.x)); dstA[5] = __uint_as_float(f2tf32(na1.y));
            dstA[6] = __uint_as_float(f2tf32(na1.z)); dstA[7] = __uint_as_float(f2tf32(na1.w));
            float* dstB = &sB[p ^ 1][bRow * BSTRIDE + bCol];
            dstB[0] = __uint_as_float(f2tf32(nb0.x)); dstB[1] = __uint_as_float(f2tf32(nb0.y));
            dstB[2] = __uint_as_float(f2tf32(nb0.z)); dstB[3] = __uint_as_float(f2tf32(nb0.w));
            dstB[4] = __uint_as_float(f2tf32(nb1.x)); dstB[5] = __uint_as_float(f2tf32(nb1.y));
            dstB[6] = __uint_as_float(f2tf32(nb1.z)); dstB[7] = __uint_as_float(f2tf32(nb1.w));
        }
        __syncthreads();
        p ^= 1;
    }

    // epilogue: c0,c1 at (row, col..col+1), c2,c3 at (row+8, col..col+1)
    #pragma unroll
    for (int nt = 0; nt < 4; nt++) {
        int col = n0 + warp_n * 32 + nt * 8 + qc * 2;
        float bx = bias[col], by = bias[col + 1];
        #pragma unroll
        for (int mt = 0; mt < 4; mt++) {
            int row = m0 + warp_m * 64 + mt * 16 + qr;
            float v0 = acc[mt][nt][0] + bx;
            float v1 = acc[mt][nt][1] + by;
            float v2 = acc[mt][nt][2] + bx;
            float v3 = acc[mt][nt][3] + by;
            if (EPI == 1) {
                v0 = gelu_exact(v0); v1 = gelu_exact(v1);
                v2 = gelu_exact(v2); v3 = gelu_exact(v3);
            }
            if (EPI == 2) {
                const float* r0 = R + (size_t)row * N + col;
                const float* r1 = R + (size_t)(row + 8) * N + col;
                float2 ra = *(const float2*)r0;
                float2 rb = *(const float2*)r1;
                v0 += ra.x; v1 += ra.y; v2 += rb.x; v3 += rb.y;
            }
            float2 oa; oa.x = v0; oa.y = v1;
            float2 ob; ob.x = v2; ob.y = v3;
            *(float2*)(C + (size_t)row * N + col)       = oa;
            *(float2*)(C + (size_t)(row + 8) * N + col) = ob;
        }
    }
}

// ---------------- per-window mean of q and k ----------------
__global__ void winmean_kernel(const float* __restrict__ QKV,
                               float* __restrict__ qw, float* __restrict__ kw) {
    int np = blockIdx.x;           // 0..391
    int c = threadIdx.x;           // 0..255
    const float* base = QKV + (size_t)np * 64 * QKC;
    float sq = 0.f, sk = 0.f;
    #pragma unroll 8
    for (int t = 0; t < 64; t++) {
        sq += base[(size_t)t * QKC + c];
        sk += base[(size_t)t * QKC + 256 + c];
    }
    qw[np * CDIM + c] = sq * (1.0f / 64.0f);
    kw[np * CDIM + c] = sk * (1.0f / 64.0f);
}

// ---------------- router logits + top-4 ----------------
__global__ void router_kernel(const float* __restrict__ qw, const float* __restrict__ kw,
                              int* __restrict__ topk) {
    int np = blockIdx.x;
    int n = np / NWIN;
    int tid = threadIdx.x;         // 64 threads
    __shared__ float qs[CDIM];
    __shared__ float lg[NWIN];
    for (int i = tid; i < CDIM; i += 64) qs[i] = qw[np * CDIM + i] * WSCALE;
    __syncthreads();
    if (tid < NWIN) {
        const float* kr = kw + (size_t)(n * NWIN + tid) * CDIM;
        float s = 0.f;
        #pragma unroll 8
        for (int c = 0; c < CDIM; c++) s += qs[c] * kr[c];
        lg[tid] = s;
    }
    __syncthreads();
    if (tid == 0) {
        bool used[NWIN];
        #pragma unroll
        for (int i = 0; i < NWIN; i++) used[i] = false;
        for (int r = 0; r < 4; r++) {
            float best = -1e30f; int bi = 0;
            for (int q = 0; q < NWIN; q++)
                if (!used[q] && lg[q] > best) { best = lg[q]; bi = q; }
            used[bi] = true;
            topk[np * 4 + r] = bi;
        }
    }
}

// ---------------- gathered attention, online softmax ----------------
// grid (392, 8 heads), 64 threads = 64 queries
__global__ void attn_kernel(const float* __restrict__ QKV, const int* __restrict__ topk,
                            float* __restrict__ O) {
    __shared__ float ks[64][32];
    __shared__ float vs[64][32];
    int np = blockIdx.x, mh = blockIdx.y;
    int n = np / NWIN, p = np % NWIN;
    int tid = threadIdx.x;

    const float* qrow = QKV + ((size_t)np * 64 + tid) * QKC + mh * 32;
    float q[32];
    #pragma unroll
    for (int i = 0; i < 32; i += 4) {
        float4 v = *(const float4*)(qrow + i);
        q[i] = v.x * WSCALE; q[i + 1] = v.y * WSCALE;
        q[i + 2] = v.z * WSCALE; q[i + 3] = v.w * WSCALE;
    }

    float mrun = -1e30f, lrun = 0.f;
    float acc[32];
    #pragma unroll
    for (int c = 0; c < 32; c++) acc[c] = 0.f;

    for (int t4 = 0; t4 < 4; t4++) {
        int r = topk[np * 4 + t4];
        const float* kbase = QKV + (size_t)(n * NWIN + r) * 64 * QKC + 256 + mh * 32;
        // stage 64x32 K and V tiles
        for (int idx = tid; idx < 512; idx += 64) {
            int rr = idx >> 3, cc = (idx & 7) * 4;
            *(float4*)&ks[rr][cc] = *(const float4*)(kbase + (size_t)rr * QKC + cc);
            *(float4*)&vs[rr][cc] = *(const float4*)(kbase + (size_t)rr * QKC + 256 + cc);
        }
        __syncthreads();

        float s[64];
        float mc = mrun;
        #pragma unroll
        for (int j = 0; j < 64; j++) {
            float d = 0.f;
            #pragma unroll
            for (int c = 0; c < 32; c++) d += q[c] * ks[j][c];
            s[j] = d;
            mc = fmaxf(mc, d);
        }
        float corr = __expf(mrun - mc);
        lrun *= corr;
        #pragma unroll
        for (int c = 0; c < 32; c++) acc[c] *= corr;
        #pragma unroll
        for (int j = 0; j < 64; j++) {
            float pj = __expf(s[j] - mc);
            lrun += pj;
            #pragma unroll
            for (int c = 0; c < 32; c++) acc[c] += pj * vs[j][c];
        }
        mrun = mc;
        __syncthreads();
    }

    float inv = 1.0f / lrun;
    int jj = p / 7, ii = p % 7, hh = tid >> 3, ww = tid & 7;
    int y = jj * 8 + hh, xx = ii * 8 + ww;
    float* orow = O + ((size_t)(n * HWDIM + y) * HWDIM + xx) * CDIM + mh * 32;
    #pragma unroll
    for (int c = 0; c < 32; c += 4) {
        float4 v;
        v.x = acc[c] * inv; v.y = acc[c + 1] * inv;
        v.z = acc[c + 2] * inv; v.w = acc[c + 3] * inv;
        *(float4*)(orow + c) = v;
    }
}

// ---------------- 5x5 depthwise lepe, accumulates into attention output ----------------
__global__ void lepe_kernel(const float* __restrict__ QKV, const float* __restrict__ W,
                            const float* __restrict__ B, float* __restrict__ O) {
    int t = blockIdx.x;
    int c = threadIdx.x;
    int n = t / 3136, rem = t % 3136;
    int y = rem / 56, x = rem % 56;
    float acc = B[c];
    #pragma unroll
    for (int dy = -2; dy <= 2; dy++) {
        int yy = y + dy;
        if (yy < 0 || yy >= 56) continue;
        #pragma unroll
        for (int dx = -2; dx <= 2; dx++) {
            int xx = x + dx;
            if (xx < 0 || xx >= 56) continue;
            int p  = (yy >> 3) * 7 + (xx >> 3);
            int qi = (yy & 7) * 8 + (xx & 7);
            size_t rowi = ((size_t)(n * NWIN + p) * 64 + qi) * QKC + 512;
            acc += QKV[rowi + c] * W[((dy + 2) * 5 + (dx + 2)) * CDIM + c];
        }
    }
    O[(size_t)t * CDIM + c] += acc;
}

// ---------------- host launch ----------------
extern "C" void kernel_launch(void* const* d_in, const int* in_sizes, int n_in,
                              void* d_out, int out_size) {
    const float* x      = (const float*)d_in[0];
    const float* ln1_g  = (const float*)d_in[1];
    const float* ln1_b  = (const float*)d_in[2];
    const float* qkv_w  = (const float*)d_in[3];
    const float* qkv_b  = (const float*)d_in[4];
    const float* lepe_w = (const float*)d_in[5];
    const float* lepe_b = (const float*)d_in[6];
    const float* wo_w   = (const float*)d_in[7];
    const float* wo_b   = (const float*)d_in[8];
    const float* ln2_g  = (const float*)d_in[9];
    const float* ln2_b  = (const float*)d_in[10];
    const float* mlp_w1 = (const float*)d_in[11];
    const float* mlp_b1 = (const float*)d_in[12];
    const float* mlp_w2 = (const float*)d_in[13];
    const float* mlp_b2 = (const float*)d_in[14];
    float* out = (float*)d_out;

    float *tmp, *qkv, *x1, *hid, *qw, *kw;
    int* tk;
    cudaGetSymbolAddress((void**)&tmp, g_tmp256);
    cudaGetSymbolAddress((void**)&qkv, g_qkv);
    cudaGetSymbolAddress((void**)&x1,  g_x1);
    cudaGetSymbolAddress((void**)&hid, g_hid);
    cudaGetSymbolAddress((void**)&qw,  g_qwin);
    cudaGetSymbolAddress((void**)&kw,  g_kwin);
    cudaGetSymbolAddress((void**)&tk,  g_topk);

    // 1. LN1 with window permute (image -> windowed token order)
    ln_kernel<true><<<TOK / 8, 256>>>(x, ln1_g, ln1_b, tmp);
    // 2. qkv GEMM: [25088,256] x [256,768]
    tgemm_kernel<0><<<dim3(QKC / 128, TOK / 128), 256>>>(tmp, qkv_w, qkv_b, nullptr, qkv,
                                                         TOK, QKC, CDIM);
    // 3. window means
    winmean_kernel<<<NPALL, 256>>>(qkv, qw, kw);
    // 4. router + top-4
    router_kernel<<<NPALL, 64>>>(qw, kw, tk);
    // 5. gathered attention (writes image order into tmp)
    attn_kernel<<<dim3(NPALL, 8), 64>>>(qkv, tk, tmp);
    // 6. lepe depthwise conv accumulates into tmp
    lepe_kernel<<<TOK, 256>>>(qkv, lepe_w, lepe_b, tmp);
    // 7. wo GEMM + residual with original x -> x1
    tgemm_kernel<2><<<dim3(CDIM / 128, TOK / 128), 256>>>(tmp, wo_w, wo_b, x, x1,
                                                          TOK, CDIM, CDIM);
    // 8. LN2 (no permute)
    ln_kernel<false><<<TOK / 8, 256>>>(x1, ln2_g, ln2_b, tmp);
    // 9. MLP1 + exact GELU
    tgemm_kernel<1><<<dim3(HIDC / 128, TOK / 128), 256>>>(tmp, mlp_w1, mlp_b1, nullptr, hid,
                                                          TOK, HIDC, CDIM);
    // 10. MLP2 + residual -> out
    tgemm_kernel<2><<<dim3(CDIM / 128, TOK / 128), 256>>>(hid, mlp_w2, mlp_b2, x1, out,
                                                          TOK, CDIM, HIDC);
}

// round 3
// speedup vs baseline: 2.0517x; 1.0784x over previous
#include <cuda_runtime.h>
#include <math.h>
#include <stdint.h>

// ---------------- problem constants ----------------
#define TOK    25088      // 8*56*56
#define NBATCH 8
#define HWDIM  56
#define CDIM   256
#define QKC    768        // qkv width
#define HIDC   1024
#define NWIN   49         // 7*7 windows per image
#define NPALL  392        // 8*49
#define WSCALE 0.0625f    // 256^-0.5

// ---------------- scratch (device globals; no allocs allowed) ----------------
__device__ float g_tmp256[TOK * CDIM];     // ln1(win-order) -> attn+lepe(img) -> ln2
__device__ float g_qkv[TOK * QKC];         // windowed token order
__device__ float g_x1[TOK * CDIM];         // after first residual
__device__ float g_hid[(size_t)TOK * HIDC];
__device__ float g_qwin[NPALL * CDIM];
__device__ float g_kwin[NPALL * CDIM];
__device__ int   g_topk[NPALL * 4];

// ---------------- LayerNorm (warp per token), optional window permute ----------------
template<bool PERM>
__global__ void ln_kernel(const float* __restrict__ X, const float* __restrict__ gam,
                          const float* __restrict__ bet, float* __restrict__ Y) {
    int warp = threadIdx.x >> 5, lane = threadIdx.x & 31;
    int t = blockIdx.x * 8 + warp;
    const float* row = X + (size_t)t * CDIM;
    float4 v0 = *(const float4*)(row + lane * 8);
    float4 v1 = *(const float4*)(row + lane * 8 + 4);
    float s  = v0.x + v0.y + v0.z + v0.w + v1.x + v1.y + v1.z + v1.w;
    float sq = v0.x*v0.x + v0.y*v0.y + v0.z*v0.z + v0.w*v0.w
             + v1.x*v1.x + v1.y*v1.y + v1.z*v1.z + v1.w*v1.w;
    #pragma unroll
    for (int o = 16; o; o >>= 1) {
        s  += __shfl_xor_sync(0xffffffffu, s, o);
        sq += __shfl_xor_sync(0xffffffffu, sq, o);
    }
    float mu  = s * (1.0f / 256.0f);
    float var = sq * (1.0f / 256.0f) - mu * mu;
    float inv = rsqrtf(var + 1e-6f);

    int orow;
    if (PERM) {
        int n = t / 3136, rem = t % 3136;
        int y = rem / 56, x = rem % 56;
        int p  = (y >> 3) * 7 + (x >> 3);
        int qi = (y & 7) * 8 + (x & 7);
        orow = (n * NWIN + p) * 64 + qi;
    } else {
        orow = t;
    }
    float4 g0 = *(const float4*)(gam + lane * 8);
    float4 g1 = *(const float4*)(gam + lane * 8 + 4);
    float4 b0 = *(const float4*)(bet + lane * 8);
    float4 b1 = *(const float4*)(bet + lane * 8 + 4);
    float4 o0, o1;
    o0.x = (v0.x - mu) * inv * g0.x + b0.x;
    o0.y = (v0.y - mu) * inv * g0.y + b0.y;
    o0.z = (v0.z - mu) * inv * g0.z + b0.z;
    o0.w = (v0.w - mu) * inv * g0.w + b0.w;
    o1.x = (v1.x - mu) * inv * g1.x + b1.x;
    o1.y = (v1.y - mu) * inv * g1.y + b1.y;
    o1.z = (v1.z - mu) * inv * g1.z + b1.z;
    o1.w = (v1.w - mu) * inv * g1.w + b1.w;
    float* orp = Y + (size_t)orow * CDIM + lane * 8;
    *(float4*)(orp)     = o0;
    *(float4*)(orp + 4) = o1;
}

// ---------------- TF32 tensor-core GEMM 128x128x16, 256 threads ----------------
__device__ __forceinline__ float gelu_exact(float x) {
    return 0.5f * x * (1.0f + erff(x * 0.70710678118654752440f));
}

__device__ __forceinline__ uint32_t f2tf32(float x) {
    uint32_t u;
    asm("cvt.rna.tf32.f32 %0, %1;" : "=r"(u) : "f"(x));
    return u;
}

#define ASTRIDE 20
#define BSTRIDE 136

template<int EPI>
__global__ __launch_bounds__(256)
void tgemm_kernel(const float* __restrict__ A, const float* __restrict__ B,
                  const float* __restrict__ bias, const float* __restrict__ R,
                  float* __restrict__ C, int M, int N, int K) {
    __shared__ float sA[2][128 * ASTRIDE];   // [m][k], k-stride padded to 20
    __shared__ float sB[2][16 * BSTRIDE];    // [k][n], n-stride padded to 136

    int tid = threadIdx.x;
    int warp = tid >> 5, lane = tid & 31;
    int qr = lane >> 2, qc = lane & 3;
    int warp_m = warp >> 2, warp_n = warp & 3;   // 2 x 4
    int m0 = blockIdx.y * 128, n0 = blockIdx.x * 128;

    int aRow = tid >> 1, aCol = (tid & 1) * 8;   // 128 rows x 16 k
    int bRow = tid >> 4, bCol = (tid & 15) * 8;  // 16 k x 128 n
    const float* Ag = A + (size_t)(m0 + aRow) * K + aCol;
    const float* Bg = B + (size_t)bRow * N + n0 + bCol;

    float acc[4][4][4];
    #pragma unroll
    for (int i = 0; i < 4; i++)
        #pragma unroll
        for (int j = 0; j < 4; j++)
            #pragma unroll
            for (int v = 0; v < 4; v++) acc[i][j][v] = 0.0f;

    {
        float4 a0 = *(const float4*)(Ag);
        float4 a1 = *(const float4*)(Ag + 4);
        float4 b0 = *(const float4*)(Bg);
        float4 b1 = *(const float4*)(Bg + 4);
        float* dstA = &sA[0][aRow * ASTRIDE + aCol];
        dstA[0] = __uint_as_float(f2tf32(a0.x)); dstA[1] = __uint_as_float(f2tf32(a0.y));
        dstA[2] = __uint_as_float(f2tf32(a0.z)); dstA[3] = __uint_as_float(f2tf32(a0.w));
        dstA[4] = __uint_as_float(f2tf32(a1.x)); dstA[5] = __uint_as_float(f2tf32(a1.y));
        dstA[6] = __uint_as_float(f2tf32(a1.z)); dstA[7] = __uint_as_float(f2tf32(a1.w));
        float* dstB = &sB[0][bRow * BSTRIDE + bCol];
        dstB[0] = __uint_as_float(f2tf32(b0.x)); dstB[1] = __uint_as_float(f2tf32(b0.y));
        dstB[2] = __uint_as_float(f2tf32(b0.z)); dstB[3] = __uint_as_float(f2tf32(b0.w));
        dstB[4] = __uint_as_float(f2tf32(b1.x)); dstB[5] = __uint_as_float(f2tf32(b1.y));
        dstB[6] = __uint_as_float(f2tf32(b1.z)); dstB[7] = __uint_as_float(f2tf32(b1.w));
    }
    __syncthreads();

    int p = 0;
    for (int k0 = 0; k0 < K; k0 += 16) {
        bool more = (k0 + 16) < K;
        float4 na0, na1, nb0, nb1;
        if (more) {
            na0 = *(const float4*)(Ag + k0 + 16);
            na1 = *(const float4*)(Ag + k0 + 20);
            nb0 = *(const float4*)(Bg + (size_t)(k0 + 16) * N);
            nb1 = *(const float4*)(Bg + (size_t)(k0 + 16) * N + 4);
        }

        const float* Ab = sA[p];
        const float* Bb = sB[p];
        #pragma unroll
        for (int ks = 0; ks < 16; ks += 8) {
            uint32_t af[4][4], bf[4][2];
            #pragma unroll
            for (int mt = 0; mt < 4; mt++) {
                int r = warp_m * 64 + mt * 16 + qr;
                af[mt][0] = __float_as_uint(Ab[(r)     * ASTRIDE + ks + qc]);
                af[mt][1] = __float_as_uint(Ab[(r + 8) * ASTRIDE + ks + qc]);
                af[mt][2] = __float_as_uint(Ab[(r)     * ASTRIDE + ks + qc + 4]);
                af[mt][3] = __float_as_uint(Ab[(r + 8) * ASTRIDE + ks + qc + 4]);
            }
            #pragma unroll
            for (int nt = 0; nt < 4; nt++) {
                int cn = warp_n * 32 + nt * 8 + qr;
                bf[nt][0] = __float_as_uint(Bb[(ks + qc)     * BSTRIDE + cn]);
                bf[nt][1] = __float_as_uint(Bb[(ks + qc + 4) * BSTRIDE + cn]);
            }
            #pragma unroll
            for (int mt = 0; mt < 4; mt++)
                #pragma unroll
                for (int nt = 0; nt < 4; nt++) {
                    asm volatile(
                        "mma.sync.aligned.m16n8k8.row.col.f32.tf32.tf32.f32 "
                        "{%0,%1,%2,%3}, {%4,%5,%6,%7}, {%8,%9}, {%0,%1,%2,%3};"
                        : "+f"(acc[mt][nt][0]), "+f"(acc[mt][nt][1]),
                          "+f"(acc[mt][nt][2]), "+f"(acc[mt][nt][3])
                        : "r"(af[mt][0]), "r"(af[mt][1]), "r"(af[mt][2]), "r"(af[mt][3]),
                          "r"(bf[nt][0]), "r"(bf[nt][1]));
                }
        }

        if (more) {
            float* dstA = &sA[p ^ 1][aRow * ASTRIDE + aCol];
            dstA[0] = __uint_as_float(f2tf32(na0.x)); dstA[1] = __uint_as_float(f2tf32(na0.y));
            dstA[2] = __uint_as_float(f2tf32(na0.z)); dstA[3] = __uint_as_float(f2tf32(na0.w));
            dstA[4] = __uint_as_float(f2tf32(na1.x)); dstA[5] = __uint_as_float(f2tf32(na1.y));
            dstA[6] = __uint_as_float(f2tf32(na1.z)); dstA[7] = __uint_as_float(f2tf32(na1.w));
            float* dstB = &sB[p ^ 1][bRow * BSTRIDE + bCol];
            dstB[0] = __uint_as_float(f2tf32(nb0.x)); dstB[1] = __uint_as_float(f2tf32(nb0.y));
            dstB[2] = __uint_as_float(f2tf32(nb0.z)); dstB[3] = __uint_as_float(f2tf32(nb0.w));
            dstB[4] = __uint_as_float(f2tf32(nb1.x)); dstB[5] = __uint_as_float(f2tf32(nb1.y));
            dstB[6] = __uint_as_float(f2tf32(nb1.z)); dstB[7] = __uint_as_float(f2tf32(nb1.w));
        }
        __syncthreads();
        p ^= 1;
    }

    #pragma unroll
    for (int nt = 0; nt < 4; nt++) {
        int col = n0 + warp_n * 32 + nt * 8 + qc * 2;
        float bx = bias[col], by = bias[col + 1];
        #pragma unroll
        for (int mt = 0; mt < 4; mt++) {
            int row = m0 + warp_m * 64 + mt * 16 + qr;
            float v0 = acc[mt][nt][0] + bx;
            float v1 = acc[mt][nt][1] + by;
            float v2 = acc[mt][nt][2] + bx;
            float v3 = acc[mt][nt][3] + by;
            if (EPI == 1) {
                v0 = gelu_exact(v0); v1 = gelu_exact(v1);
                v2 = gelu_exact(v2); v3 = gelu_exact(v3);
            }
            if (EPI == 2) {
                const float* r0 = R + (size_t)row * N + col;
                const float* r1 = R + (size_t)(row + 8) * N + col;
                float2 ra = *(const float2*)r0;
                float2 rb = *(const float2*)r1;
                v0 += ra.x; v1 += ra.y; v2 += rb.x; v3 += rb.y;
            }
            float2 oa; oa.x = v0; oa.y = v1;
            float2 ob; ob.x = v2; ob.y = v3;
            *(float2*)(C + (size_t)row * N + col)       = oa;
            *(float2*)(C + (size_t)(row + 8) * N + col) = ob;
        }
    }
}

// ---------------- per-window mean of q and k ----------------
__global__ void winmean_kernel(const float* __restrict__ QKV,
                               float* __restrict__ qw, float* __restrict__ kw) {
    int np = blockIdx.x;           // 0..391
    int c = threadIdx.x;           // 0..255
    const float* base = QKV + (size_t)np * 64 * QKC;
    float sq = 0.f, sk = 0.f;
    #pragma unroll 8
    for (int t = 0; t < 64; t++) {
        sq += base[(size_t)t * QKC + c];
        sk += base[(size_t)t * QKC + 256 + c];
    }
    qw[np * CDIM + c] = sq * (1.0f / 64.0f);
    kw[np * CDIM + c] = sk * (1.0f / 64.0f);
}

// ---------------- router: warp-per-logit, coalesced + shfl reduce ----------------
__global__ void router_kernel(const float* __restrict__ qw, const float* __restrict__ kw,
                              int* __restrict__ topk) {
    int np = blockIdx.x;
    int n = np / NWIN;
    int tid = threadIdx.x;         // 256 threads = 8 warps
    int warp = tid >> 5, lane = tid & 31;
    __shared__ float qs[CDIM];
    __shared__ float lg[64];
    qs[tid] = qw[np * CDIM + tid] * WSCALE;
    __syncthreads();
    for (int q = warp; q < NWIN; q += 8) {
        const float* kr = kw + (size_t)(n * NWIN + q) * CDIM;
        float s = 0.f;
        #pragma unroll
        for (int h = 0; h < 2; h++) {
            float4 kv = ((const float4*)kr)[h * 32 + lane];
            float4 qv = ((const float4*)qs)[h * 32 + lane];
            s += kv.x * qv.x + kv.y * qv.y + kv.z * qv.z + kv.w * qv.w;
        }
        #pragma unroll
        for (int o = 16; o; o >>= 1) s += __shfl_xor_sync(0xffffffffu, s, o);
        if (lane == 0) lg[q] = s;
    }
    __syncthreads();
    if (tid == 0) {
        bool used[NWIN];
        #pragma unroll
        for (int i = 0; i < NWIN; i++) used[i] = false;
        for (int r = 0; r < 4; r++) {
            float best = -1e30f; int bi = 0;
            for (int q = 0; q < NWIN; q++)
                if (!used[q] && lg[q] > best) { best = lg[q]; bi = q; }
            used[bi] = true;
            topk[np * 4 + r] = bi;
        }
    }
}

// ---------------- gathered attention, online softmax (float4 smem reads) ----------------
// grid (392, 8 heads), 64 threads = 64 queries
__global__ void attn_kernel(const float* __restrict__ QKV, const int* __restrict__ topk,
                            float* __restrict__ O) {
    __shared__ float ks[64][32];
    __shared__ float vs[64][32];
    int np = blockIdx.x, mh = blockIdx.y;
    int n = np / NWIN, p = np % NWIN;
    int tid = threadIdx.x;

    const float* qrow = QKV + ((size_t)np * 64 + tid) * QKC + mh * 32;
    float4 q[8];
    #pragma unroll
    for (int i = 0; i < 8; i++) {
        float4 v = *(const float4*)(qrow + i * 4);
        v.x *= WSCALE; v.y *= WSCALE; v.z *= WSCALE; v.w *= WSCALE;
        q[i] = v;
    }

    float mrun = -1e30f, lrun = 0.f;
    float4 acc[8];
    #pragma unroll
    for (int i = 0; i < 8; i++) { acc[i].x = 0.f; acc[i].y = 0.f; acc[i].z = 0.f; acc[i].w = 0.f; }

    for (int t4 = 0; t4 < 4; t4++) {
        int r = topk[np * 4 + t4];
        const float* kbase = QKV + (size_t)(n * NWIN + r) * 64 * QKC + 256 + mh * 32;
        for (int idx = tid; idx < 512; idx += 64) {
            int rr = idx >> 3, cc = (idx & 7) * 4;
            *(float4*)&ks[rr][cc] = *(const float4*)(kbase + (size_t)rr * QKC + cc);
            *(float4*)&vs[rr][cc] = *(const float4*)(kbase + (size_t)rr * QKC + 256 + cc);
        }
        __syncthreads();

        #pragma unroll
        for (int half = 0; half < 2; half++) {
            float s[32];
            float mc = mrun;
            #pragma unroll
            for (int j = 0; j < 32; j++) {
                int j2 = half * 32 + j;
                float d = 0.f;
                #pragma unroll
                for (int c4 = 0; c4 < 8; c4++) {
                    float4 k4 = *(const float4*)&ks[j2][c4 * 4];
                    d += q[c4].x * k4.x + q[c4].y * k4.y + q[c4].z * k4.z + q[c4].w * k4.w;
                }
                s[j] = d;
                mc = fmaxf(mc, d);
            }
            float corr = __expf(mrun - mc);
            lrun *= corr;
            #pragma unroll
            for (int i = 0; i < 8; i++) {
                acc[i].x *= corr; acc[i].y *= corr; acc[i].z *= corr; acc[i].w *= corr;
            }
            #pragma unroll
            for (int j = 0; j < 32; j++) {
                int j2 = half * 32 + j;
                float pj = __expf(s[j] - mc);
                lrun += pj;
                #pragma unroll
                for (int c4 = 0; c4 < 8; c4++) {
                    float4 v4 = *(const float4*)&vs[j2][c4 * 4];
                    acc[c4].x += pj * v4.x; acc[c4].y += pj * v4.y;
                    acc[c4].z += pj * v4.z; acc[c4].w += pj * v4.w;
                }
            }
            mrun = mc;
        }
        __syncthreads();
    }

    float inv = 1.0f / lrun;
    int jj = p / 7, ii = p % 7, hh = tid >> 3, ww = tid & 7;
    int y = jj * 8 + hh, xx = ii * 8 + ww;
    float* orow = O + ((size_t)(n * HWDIM + y) * HWDIM + xx) * CDIM + mh * 32;
    #pragma unroll
    for (int c4 = 0; c4 < 8; c4++) {
        float4 v;
        v.x = acc[c4].x * inv; v.y = acc[c4].y * inv;
        v.z = acc[c4].z * inv; v.w = acc[c4].w * inv;
        *(float4*)(orow + c4 * 4) = v;
    }
}

// ---------------- 5x5 depthwise lepe, smem-tiled, accumulates into O ----------------
// grid (392 windows, 4 channel groups of 64), 256 threads
__global__ __launch_bounds__(256)
void lepe_kernel(const float* __restrict__ QKV, const float* __restrict__ W,
                 const float* __restrict__ B, float* __restrict__ O) {
    __shared__ float sv[144][64];   // 12x12 halo tile x 64 channels
    __shared__ float sw[25][64];
    int np = blockIdx.x, cg = blockIdx.y;
    int n = np / NWIN, p = np % NWIN;
    int jj = p / 7, ii = p % 7;
    int tid = threadIdx.x;

    // stage weights: 25 taps x 64 ch
    for (int i = tid; i < 1600; i += 256)
        sw[i / 64][i % 64] = W[(i / 64) * CDIM + cg * 64 + (i % 64)];

    // stage values: 144 positions x 16 float4 = 2304 float4 loads
    for (int i = tid; i < 2304; i += 256) {
        int pos = i >> 4, c4 = i & 15;
        int yy = jj * 8 + (pos / 12) - 2;
        int xx = ii * 8 + (pos % 12) - 2;
        float4 v = make_float4(0.f, 0.f, 0.f, 0.f);
        if (yy >= 0 && yy < HWDIM && xx >= 0 && xx < HWDIM) {
            int pp = (yy >> 3) * 7 + (xx >> 3);
            int qi = (yy & 7) * 8 + (xx & 7);
            const float* src = QKV + ((size_t)(n * NWIN + pp) * 64 + qi) * QKC + 512 + cg * 64;
            v = *(const float4*)(src + c4 * 4);
        }
        *(float4*)&sv[pos][c4 * 4] = v;
    }
    __syncthreads();

    int c = tid & 63, pp0 = tid >> 6;    // pp0 in 0..3
    float wr[25];
    #pragma unroll
    for (int t5 = 0; t5 < 25; t5++) wr[t5] = sw[t5][c];
    float bias = B[cg * 64 + c];

    #pragma unroll
    for (int hi = 0; hi < 2; hi++) {
        int hh = pp0 + hi * 4;
        #pragma unroll
        for (int ww = 0; ww < 8; ww++) {
            float acc = bias;
            #pragma unroll
            for (int dy = 0; dy < 5; dy++)
                #pragma unroll
                for (int dx = 0; dx < 5; dx++)
                    acc += sv[(hh + dy) * 12 + (ww + dx)][c] * wr[dy * 5 + dx];
            int y = jj * 8 + hh, x = ii * 8 + ww;
            int t = (n * HWDIM + y) * HWDIM + x;
            O[(size_t)t * CDIM + cg * 64 + c] += acc;
        }
    }
}

// ---------------- host launch ----------------
extern "C" void kernel_launch(void* const* d_in, const int* in_sizes, int n_in,
                              void* d_out, int out_size) {
    const float* x      = (const float*)d_in[0];
    const float* ln1_g  = (const float*)d_in[1];
    const float* ln1_b  = (const float*)d_in[2];
    const float* qkv_w  = (const float*)d_in[3];
    const float* qkv_b  = (const float*)d_in[4];
    const float* lepe_w = (const float*)d_in[5];
    const float* lepe_b = (const float*)d_in[6];
    const float* wo_w   = (const float*)d_in[7];
    const float* wo_b   = (const float*)d_in[8];
    const float* ln2_g  = (const float*)d_in[9];
    const float* ln2_b  = (const float*)d_in[10];
    const float* mlp_w1 = (const float*)d_in[11];
    const float* mlp_b1 = (const float*)d_in[12];
    const float* mlp_w2 = (const float*)d_in[13];
    const float* mlp_b2 = (const float*)d_in[14];
    float* out = (float*)d_out;

    float *tmp, *qkv, *x1, *hid, *qw, *kw;
    int* tk;
    cudaGetSymbolAddress((void**)&tmp, g_tmp256);
    cudaGetSymbolAddress((void**)&qkv, g_qkv);
    cudaGetSymbolAddress((void**)&x1,  g_x1);
    cudaGetSymbolAddress((void**)&hid, g_hid);
    cudaGetSymbolAddress((void**)&qw,  g_qwin);
    cudaGetSymbolAddress((void**)&kw,  g_kwin);
    cudaGetSymbolAddress((void**)&tk,  g_topk);

    // 1. LN1 with window permute (image -> windowed token order)
    ln_kernel<true><<<TOK / 8, 256>>>(x, ln1_g, ln1_b, tmp);
    // 2. qkv GEMM: [25088,256] x [256,768]
    tgemm_kernel<0><<<dim3(QKC / 128, TOK / 128), 256>>>(tmp, qkv_w, qkv_b, nullptr, qkv,
                                                         TOK, QKC, CDIM);
    // 3. window means
    winmean_kernel<<<NPALL, 256>>>(qkv, qw, kw);
    // 4. router + top-4
    router_kernel<<<NPALL, 256>>>(qkv ? qw : qw, kw, tk);
    // 5. gathered attention (writes image order into tmp)
    attn_kernel<<<dim3(NPALL, 8), 64>>>(qkv, tk, tmp);
    // 6. lepe depthwise conv accumulates into tmp
    lepe_kernel<<<dim3(NPALL, 4), 256>>>(qkv, lepe_w, lepe_b, tmp);
    // 7. wo GEMM + residual with original x -> x1
    tgemm_kernel<2><<<dim3(CDIM / 128, TOK / 128), 256>>>(tmp, wo_w, wo_b, x, x1,
                                                          TOK, CDIM, CDIM);
    // 8. LN2 (no permute)
    ln_kernel<false><<<TOK / 8, 256>>>(x1, ln2_g, ln2_b, tmp);
    // 9. MLP1 + exact GELU
    tgemm_kernel<1><<<dim3(HIDC / 128, TOK / 128), 256>>>(tmp, mlp_w1, mlp_b1, nullptr, hid,
                                                          TOK, HIDC, CDIM);
    // 10. MLP2 + residual -> out
    tgemm_kernel<2><<<dim3(CDIM / 128, TOK / 128), 256>>>(hid, mlp_w2, mlp_b2, x1, out,
                                                          TOK, CDIM, HIDC);
}

// round 6
// speedup vs baseline: 2.7871x; 1.3584x over previous
#include <cuda_runtime.h>
#include <math.h>
#include <stdint.h>

// ---------------- problem constants ----------------
#define TOK    25088      // 8*56*56
#define NBATCH 8
#define HWDIM  56
#define CDIM   256
#define QKC    768        // qkv width
#define HIDC   1024
#define NWIN   49         // 7*7 windows per image
#define NPALL  392        // 8*49
#define WSCALE 0.0625f    // 256^-0.5

// ---------------- scratch (device globals; no allocs allowed) ----------------
__device__ float g_tmp256[TOK * CDIM];     // ln1(win-order) -> attn+lepe(img) -> ln2
__device__ float g_qkv[TOK * QKC];         // windowed token order
__device__ float g_x1[TOK * CDIM];         // after first residual
__device__ float g_hid[(size_t)TOK * HIDC];
__device__ float g_qwin[NPALL * CDIM];
__device__ float g_kwin[NPALL * CDIM];
__device__ int   g_topk[NPALL * 4];

__device__ __forceinline__ uint32_t f2tf32(float x) {
    uint32_t u;
    asm("cvt.rna.tf32.f32 %0, %1;" : "=r"(u) : "f"(x));
    return u;
}
__device__ __forceinline__ float tf32f(float x) { return __uint_as_float(f2tf32(x)); }

// ---------------- LayerNorm (warp per token), optional window permute ----------------
template<bool PERM>
__global__ void ln_kernel(const float* __restrict__ X, const float* __restrict__ gam,
                          const float* __restrict__ bet, float* __restrict__ Y) {
    int warp = threadIdx.x >> 5, lane = threadIdx.x & 31;
    int t = blockIdx.x * 8 + warp;
    const float* row = X + (size_t)t * CDIM;
    float4 v0 = *(const float4*)(row + lane * 8);
    float4 v1 = *(const float4*)(row + lane * 8 + 4);
    float s  = v0.x + v0.y + v0.z + v0.w + v1.x + v1.y + v1.z + v1.w;
    float sq = v0.x*v0.x + v0.y*v0.y + v0.z*v0.z + v0.w*v0.w
             + v1.x*v1.x + v1.y*v1.y + v1.z*v1.z + v1.w*v1.w;
    #pragma unroll
    for (int o = 16; o; o >>= 1) {
        s  += __shfl_xor_sync(0xffffffffu, s, o);
        sq += __shfl_xor_sync(0xffffffffu, sq, o);
    }
    float mu  = s * (1.0f / 256.0f);
    float var = sq * (1.0f / 256.0f) - mu * mu;
    float inv = rsqrtf(var + 1e-6f);

    int orow;
    if (PERM) {
        int n = t / 3136, rem = t % 3136;
        int y = rem / 56, x = rem % 56;
        int p  = (y >> 3) * 7 + (x >> 3);
        int qi = (y & 7) * 8 + (x & 7);
        orow = (n * NWIN + p) * 64 + qi;
    } else {
        orow = t;
    }
    float4 g0 = *(const float4*)(gam + lane * 8);
    float4 g1 = *(const float4*)(gam + lane * 8 + 4);
    float4 b0 = *(const float4*)(bet + lane * 8);
    float4 b1 = *(const float4*)(bet + lane * 8 + 4);
    float4 o0, o1;
    o0.x = (v0.x - mu) * inv * g0.x + b0.x;
    o0.y = (v0.y - mu) * inv * g0.y + b0.y;
    o0.z = (v0.z - mu) * inv * g0.z + b0.z;
    o0.w = (v0.w - mu) * inv * g0.w + b0.w;
    o1.x = (v1.x - mu) * inv * g1.x + b1.x;
    o1.y = (v1.y - mu) * inv * g1.y + b1.y;
    o1.z = (v1.z - mu) * inv * g1.z + b1.z;
    o1.w = (v1.w - mu) * inv * g1.w + b1.w;
    float* orp = Y + (size_t)orow * CDIM + lane * 8;
    *(float4*)(orp)     = o0;
    *(float4*)(orp + 4) = o1;
}

// ---------------- TF32 tensor-core GEMM 128x128x16, 256 threads ----------------
__device__ __forceinline__ float gelu_exact(float x) {
    return 0.5f * x * (1.0f + erff(x * 0.70710678118654752440f));
}

#define ASTRIDE 20
#define BSTRIDE 136

template<int EPI>
__global__ __launch_bounds__(256)
void tgemm_kernel(const float* __restrict__ A, const float* __restrict__ B,
                  const float* __restrict__ bias, const float* __restrict__ R,
                  float* __restrict__ C, int M, int N, int K) {
    __shared__ float sA[2][128 * ASTRIDE];   // [m][k], k-stride padded to 20
    __shared__ float sB[2][16 * BSTRIDE];    // [k][n], n-stride padded to 136

    int tid = threadIdx.x;
    int warp = tid >> 5, lane = tid & 31;
    int qr = lane >> 2, qc = lane & 3;
    int warp_m = warp >> 2, warp_n = warp & 3;   // 2 x 4
    int m0 = blockIdx.y * 128, n0 = blockIdx.x * 128;

    int aRow = tid >> 1, aCol = (tid & 1) * 8;   // 128 rows x 16 k
    int bRow = tid >> 4, bCol = (tid & 15) * 8;  // 16 k x 128 n
    const float* Ag = A + (size_t)(m0 + aRow) * K + aCol;
    const float* Bg = B + (size_t)bRow * N + n0 + bCol;

    float acc[4][4][4];
    #pragma unroll
    for (int i = 0; i < 4; i++)
        #pragma unroll
        for (int j = 0; j < 4; j++)
            #pragma unroll
            for (int v = 0; v < 4; v++) acc[i][j][v] = 0.0f;

    {
        float4 a0 = *(const float4*)(Ag);
        float4 a1 = *(const float4*)(Ag + 4);
        float4 b0 = *(const float4*)(Bg);
        float4 b1 = *(const float4*)(Bg + 4);
        float* dstA = &sA[0][aRow * ASTRIDE + aCol];
        dstA[0] = tf32f(a0.x); dstA[1] = tf32f(a0.y);
        dstA[2] = tf32f(a0.z); dstA[3] = tf32f(a0.w);
        dstA[4] = tf32f(a1.x); dstA[5] = tf32f(a1.y);
        dstA[6] = tf32f(a1.z); dstA[7] = tf32f(a1.w);
        float* dstB = &sB[0][bRow * BSTRIDE + bCol];
        dstB[0] = tf32f(b0.x); dstB[1] = tf32f(b0.y);
        dstB[2] = tf32f(b0.z); dstB[3] = tf32f(b0.w);
        dstB[4] = tf32f(b1.x); dstB[5] = tf32f(b1.y);
        dstB[6] = tf32f(b1.z); dstB[7] = tf32f(b1.w);
    }
    __syncthreads();

    int p = 0;
    for (int k0 = 0; k0 < K; k0 += 16) {
        bool more = (k0 + 16) < K;
        float4 na0, na1, nb0, nb1;
        if (more) {
            na0 = *(const float4*)(Ag + k0 + 16);
            na1 = *(const float4*)(Ag + k0 + 20);
            nb0 = *(const float4*)(Bg + (size_t)(k0 + 16) * N);
            nb1 = *(const float4*)(Bg + (size_t)(k0 + 16) * N + 4);
        }

        const float* Ab = sA[p];
        const float* Bb = sB[p];
        #pragma unroll
        for (int ks = 0; ks < 16; ks += 8) {
            uint32_t af[4][4], bf[4][2];
            #pragma unroll
            for (int mt = 0; mt < 4; mt++) {
                int r = warp_m * 64 + mt * 16 + qr;
                af[mt][0] = __float_as_uint(Ab[(r)     * ASTRIDE + ks + qc]);
                af[mt][1] = __float_as_uint(Ab[(r + 8) * ASTRIDE + ks + qc]);
                af[mt][2] = __float_as_uint(Ab[(r)     * ASTRIDE + ks + qc + 4]);
                af[mt][3] = __float_as_uint(Ab[(r + 8) * ASTRIDE + ks + qc + 4]);
            }
            #pragma unroll
            for (int nt = 0; nt < 4; nt++) {
                int cn = warp_n * 32 + nt * 8 + qr;
                bf[nt][0] = __float_as_uint(Bb[(ks + qc)     * BSTRIDE + cn]);
                bf[nt][1] = __float_as_uint(Bb[(ks + qc + 4) * BSTRIDE + cn]);
            }
            #pragma unroll
            for (int mt = 0; mt < 4; mt++)
                #pragma unroll
                for (int nt = 0; nt < 4; nt++) {
                    asm volatile(
                        "mma.sync.aligned.m16n8k8.row.col.f32.tf32.tf32.f32 "
                        "{%0,%1,%2,%3}, {%4,%5,%6,%7}, {%8,%9}, {%0,%1,%2,%3};"
                        : "+f"(acc[mt][nt][0]), "+f"(acc[mt][nt][1]),
                          "+f"(acc[mt][nt][2]), "+f"(acc[mt][nt][3])
                        : "r"(af[mt][0]), "r"(af[mt][1]), "r"(af[mt][2]), "r"(af[mt][3]),
                          "r"(bf[nt][0]), "r"(bf[nt][1]));
                }
        }

        if (more) {
            float* dstA = &sA[p ^ 1][aRow * ASTRIDE + aCol];
            dstA[0] = tf32f(na0.x); dstA[1] = tf32f(na0.y);
            dstA[2] = tf32f(na0.z); dstA[3] = tf32f(na0.w);
            dstA[4] = tf32f(na1.x); dstA[5] = tf32f(na1.y);
            dstA[6] = tf32f(na1.z); dstA[7] = tf32f(na1.w);
            float* dstB = &sB[p ^ 1][bRow * BSTRIDE + bCol];
            dstB[0] = tf32f(nb0.x); dstB[1] = tf32f(nb0.y);
            dstB[2] = tf32f(nb0.z); dstB[3] = tf32f(nb0.w);
            dstB[4] = tf32f(nb1.x); dstB[5] = tf32f(nb1.y);
            dstB[6] = tf32f(nb1.z); dstB[7] = tf32f(nb1.w);
        }
        __syncthreads();
        p ^= 1;
    }

    #pragma unroll
    for (int nt = 0; nt < 4; nt++) {
        int col = n0 + warp_n * 32 + nt * 8 + qc * 2;
        float bx = bias[col], by = bias[col + 1];
        #pragma unroll
        for (int mt = 0; mt < 4; mt++) {
            int row = m0 + warp_m * 64 + mt * 16 + qr;
            float v0 = acc[mt][nt][0] + bx;
            float v1 = acc[mt][nt][1] + by;
            float v2 = acc[mt][nt][2] + bx;
            float v3 = acc[mt][nt][3] + by;
            if (EPI == 1) {
                v0 = gelu_exact(v0); v1 = gelu_exact(v1);
                v2 = gelu_exact(v2); v3 = gelu_exact(v3);
            }
            if (EPI == 2) {
                const float* r0 = R + (size_t)row * N + col;
                const float* r1 = R + (size_t)(row + 8) * N + col;
                float2 ra = *(const float2*)r0;
                float2 rb = *(const float2*)r1;
                v0 += ra.x; v1 += ra.y; v2 += rb.x; v3 += rb.y;
            }
            float2 oa; oa.x = v0; oa.y = v1;
            float2 ob; ob.x = v2; ob.y = v3;
            *(float2*)(C + (size_t)row * N + col)       = oa;
            *(float2*)(C + (size_t)(row + 8) * N + col) = ob;
        }
    }
}

// ---------------- per-window mean of q and k ----------------
__global__ void winmean_kernel(const float* __restrict__ QKV,
                               float* __restrict__ qw, float* __restrict__ kw) {
    int np = blockIdx.x;           // 0..391
    int c = threadIdx.x;           // 0..255
    const float* base = QKV + (size_t)np * 64 * QKC;
    float sq = 0.f, sk = 0.f;
    #pragma unroll 8
    for (int t = 0; t < 64; t++) {
        sq += base[(size_t)t * QKC + c];
        sk += base[(size_t)t * QKC + 256 + c];
    }
    qw[np * CDIM + c] = sq * (1.0f / 64.0f);
    kw[np * CDIM + c] = sk * (1.0f / 64.0f);
}

// ---------------- router: warp-per-logit, coalesced + shfl reduce ----------------
__global__ void router_kernel(const float* __restrict__ qw, const float* __restrict__ kw,
                              int* __restrict__ topk) {
    int np = blockIdx.x;
    int n = np / NWIN;
    int tid = threadIdx.x;         // 256 threads = 8 warps
    int warp = tid >> 5, lane = tid & 31;
    __shared__ float qs[CDIM];
    __shared__ float lg[64];
    qs[tid] = qw[np * CDIM + tid] * WSCALE;
    __syncthreads();
    for (int q = warp; q < NWIN; q += 8) {
        const float* kr = kw + (size_t)(n * NWIN + q) * CDIM;
        float s = 0.f;
        #pragma unroll
        for (int h = 0; h < 2; h++) {
            float4 kv = ((const float4*)kr)[h * 32 + lane];
            float4 qv = ((const float4*)qs)[h * 32 + lane];
            s += kv.x * qv.x + kv.y * qv.y + kv.z * qv.z + kv.w * qv.w;
        }
        #pragma unroll
        for (int o = 16; o; o >>= 1) s += __shfl_xor_sync(0xffffffffu, s, o);
        if (lane == 0) lg[q] = s;
    }
    __syncthreads();
    if (tid == 0) {
        bool used[NWIN];
        #pragma unroll
        for (int i = 0; i < NWIN; i++) used[i] = false;
        for (int r = 0; r < 4; r++) {
            float best = -1e30f; int bi = 0;
            for (int q = 0; q < NWIN; q++)
                if (!used[q] && lg[q] > best) { best = lg[q]; bi = q; }
            used[bi] = true;
            topk[np * 4 + r] = bi;
        }
    }
}

// ---------------- tensor-core gathered attention (TF32 mma), online softmax ----------
// grid (392, 8 heads), 64 threads = 2 warps; warp w owns query rows [w*32, w*32+32)
#define KS_STRIDE 36
#define VS_STRIDE 40
#define PS_STRIDE 68
__global__ __launch_bounds__(64)
void attn_kernel(const float* __restrict__ QKV, const int* __restrict__ topk,
                 float* __restrict__ O) {
    __shared__ float ks[64][KS_STRIDE];
    __shared__ float vs[64][VS_STRIDE];
    __shared__ float ps[64][PS_STRIDE];   // Q stage first, then per-warp P (warp w: rows w*32..)

    int np = blockIdx.x, mh = blockIdx.y;
    int n = np / NWIN, p = np % NWIN;
    int tid = threadIdx.x, warp = tid >> 5, lane = tid & 31;
    int qr = lane >> 2, qc = lane & 3;

    // ---- stage Q (64 x 32), scaled + tf32-rounded ----
    const float* qbase = QKV + (size_t)np * 64 * QKC + mh * 32;
    for (int i = tid; i < 512; i += 64) {
        int r = i >> 3, c = (i & 7) * 4;
        float4 v = *(const float4*)(qbase + (size_t)r * QKC + c);
        ps[r][c + 0] = tf32f(v.x * WSCALE);
        ps[r][c + 1] = tf32f(v.y * WSCALE);
        ps[r][c + 2] = tf32f(v.z * WSCALE);
        ps[r][c + 3] = tf32f(v.w * WSCALE);
    }
    __syncthreads();

    // ---- preload Q fragments: qf[mt][kk][4] covers rows warp*32+mt*16+qr{,+8}, cols kk*8+qc{,+4}
    uint32_t qf[2][4][4];
    #pragma unroll
    for (int mt = 0; mt < 2; mt++) {
        int r = warp * 32 + mt * 16 + qr;
        #pragma unroll
        for (int kk = 0; kk < 4; kk++) {
            qf[mt][kk][0] = __float_as_uint(ps[r][kk * 8 + qc]);
            qf[mt][kk][1] = __float_as_uint(ps[r + 8][kk * 8 + qc]);
            qf[mt][kk][2] = __float_as_uint(ps[r][kk * 8 + qc + 4]);
            qf[mt][kk][3] = __float_as_uint(ps[r + 8][kk * 8 + qc + 4]);
        }
    }
    __syncthreads();   // ps will be reused for P

    // online-softmax state: row index = mt*2 + half (rows mt*16+qr and mt*16+qr+8)
    float mrun[4] = {-1e30f, -1e30f, -1e30f, -1e30f};
    float lrun[4] = {0.f, 0.f, 0.f, 0.f};
    float oacc[2][4][4];
    #pragma unroll
    for (int mt = 0; mt < 2; mt++)
        #pragma unroll
        for (int nt = 0; nt < 4; nt++)
            #pragma unroll
            for (int v = 0; v < 4; v++) oacc[mt][nt][v] = 0.f;

    for (int t4 = 0; t4 < 4; t4++) {
        int rwin = topk[np * 4 + t4];
        const float* kb = QKV + (size_t)(n * NWIN + rwin) * 64 * QKC + 256 + mh * 32;
        // stage K, V tiles (64 x 32 each)
        for (int i = tid; i < 512; i += 64) {
            int r = i >> 3, c = (i & 7) * 4;
            float4 kv = *(const float4*)(kb + (size_t)r * QKC + c);
            ks[r][c + 0] = tf32f(kv.x); ks[r][c + 1] = tf32f(kv.y);
            ks[r][c + 2] = tf32f(kv.z); ks[r][c + 3] = tf32f(kv.w);
            float4 vv = *(const float4*)(kb + (size_t)r * QKC + 256 + c);
            vs[r][c + 0] = tf32f(vv.x); vs[r][c + 1] = tf32f(vv.y);
            vs[r][c + 2] = tf32f(vv.z); vs[r][c + 3] = tf32f(vv.w);
        }
        __syncthreads();

        // ---- S = Q K^T : sacc[mt][nt][4], S is 32(q) x 64(t) per warp ----
        float sacc[2][8][4];
        #pragma unroll
        for (int mt = 0; mt < 2; mt++)
            #pragma unroll
            for (int nt = 0; nt < 8; nt++)
                #pragma unroll
                for (int v = 0; v < 4; v++) sacc[mt][nt][v] = 0.f;

        #pragma unroll
        for (int kk = 0; kk < 4; kk++) {
            uint32_t bf[8][2];
            #pragma unroll
            for (int nt = 0; nt < 8; nt++) {
                bf[nt][0] = __float_as_uint(ks[nt * 8 + qr][kk * 8 + qc]);
                bf[nt][1] = __float_as_uint(ks[nt * 8 + qr][kk * 8 + qc + 4]);
            }
            #pragma unroll
            for (int mt = 0; mt < 2; mt++)
                #pragma unroll
                for (int nt = 0; nt < 8; nt++) {
                    asm volatile(
                        "mma.sync.aligned.m16n8k8.row.col.f32.tf32.tf32.f32 "
                        "{%0,%1,%2,%3}, {%4,%5,%6,%7}, {%8,%9}, {%0,%1,%2,%3};"
                        : "+f"(sacc[mt][nt][0]), "+f"(sacc[mt][nt][1]),
                          "+f"(sacc[mt][nt][2]), "+f"(sacc[mt][nt][3])
                        : "r"(qf[mt][kk][0]), "r"(qf[mt][kk][1]),
                          "r"(qf[mt][kk][2]), "r"(qf[mt][kk][3]),
                          "r"(bf[nt][0]), "r"(bf[nt][1]));
                }
        }

        // ---- online softmax on fragment ----
        float rmax[4] = {-1e30f, -1e30f, -1e30f, -1e30f};
        #pragma unroll
        for (int mt = 0; mt < 2; mt++)
            #pragma unroll
            for (int nt = 0; nt < 8; nt++) {
                rmax[mt * 2 + 0] = fmaxf(rmax[mt * 2 + 0], fmaxf(sacc[mt][nt][0], sacc[mt][nt][1]));
                rmax[mt * 2 + 1] = fmaxf(rmax[mt * 2 + 1], fmaxf(sacc[mt][nt][2], sacc[mt][nt][3]));
            }
        #pragma unroll
        for (int g = 0; g < 4; g++) {
            rmax[g] = fmaxf(rmax[g], __shfl_xor_sync(0xffffffffu, rmax[g], 1));
            rmax[g] = fmaxf(rmax[g], __shfl_xor_sync(0xffffffffu, rmax[g], 2));
        }
        float corr[4], mnew[4];
        #pragma unroll
        for (int g = 0; g < 4; g++) {
            mnew[g] = fmaxf(mrun[g], rmax[g]);
            corr[g] = __expf(mrun[g] - mnew[g]);
            lrun[g] *= corr[g];
            mrun[g] = mnew[g];
        }
        #pragma unroll
        for (int mt = 0; mt < 2; mt++)
            #pragma unroll
            for (int nt = 0; nt < 4; nt++) {
                oacc[mt][nt][0] *= corr[mt * 2 + 0];
                oacc[mt][nt][1] *= corr[mt * 2 + 0];
                oacc[mt][nt][2] *= corr[mt * 2 + 1];
                oacc[mt][nt][3] *= corr[mt * 2 + 1];
            }
        float psum[4] = {0.f, 0.f, 0.f, 0.f};
        #pragma unroll
        for (int mt = 0; mt < 2; mt++) {
            int r0 = warp * 32 + mt * 16 + qr;
            #pragma unroll
            for (int nt = 0; nt < 8; nt++) {
                float p0 = __expf(sacc[mt][nt][0] - mnew[mt * 2 + 0]);
                float p1 = __expf(sacc[mt][nt][1] - mnew[mt * 2 + 0]);
                float p2 = __expf(sacc[mt][nt][2] - mnew[mt * 2 + 1]);
                float p3 = __expf(sacc[mt][nt][3] - mnew[mt * 2 + 1]);
                psum[mt * 2 + 0] += p0 + p1;
                psum[mt * 2 + 1] += p2 + p3;
                float2 w0; w0.x = tf32f(p0); w0.y = tf32f(p1);
                float2 w1; w1.x = tf32f(p2); w1.y = tf32f(p3);
                *(float2*)&ps[r0][nt * 8 + qc * 2]     = w0;
                *(float2*)&ps[r0 + 8][nt * 8 + qc * 2] = w1;
            }
        }
        #pragma unroll
        for (int g = 0; g < 4; g++) {
            psum[g] += __shfl_xor_sync(0xffffffffu, psum[g], 1);
            psum[g] += __shfl_xor_sync(0xffffffffu, psum[g], 2);
            lrun[g] += psum[g];
        }
        __syncwarp();

        // ---- O += P V : k = 64 tokens ----
        #pragma unroll
        for (int kt = 0; kt < 8; kt++) {
            uint32_t af[2][4], bf[4][2];
            #pragma unroll
            for (int mt = 0; mt < 2; mt++) {
                int r = warp * 32 + mt * 16 + qr;
                af[mt][0] = __float_as_uint(ps[r][kt * 8 + qc]);
                af[mt][1] = __float_as_uint(ps[r + 8][kt * 8 + qc]);
                af[mt][2] = __float_as_uint(ps[r][kt * 8 + qc + 4]);
                af[mt][3] = __float_as_uint(ps[r + 8][kt * 8 + qc + 4]);
            }
            #pragma unroll
            for (int nt = 0; nt < 4; nt++) {
                bf[nt][0] = __float_as_uint(vs[kt * 8 + qc][nt * 8 + qr]);
                bf[nt][1] = __float_as_uint(vs[kt * 8 + qc + 4][nt * 8 + qr]);
            }
            #pragma unroll
            for (int mt = 0; mt < 2; mt++)
                #pragma unroll
                for (int nt = 0; nt < 4; nt++) {
                    asm volatile(
                        "mma.sync.aligned.m16n8k8.row.col.f32.tf32.tf32.f32 "
                        "{%0,%1,%2,%3}, {%4,%5,%6,%7}, {%8,%9}, {%0,%1,%2,%3};"
                        : "+f"(oacc[mt][nt][0]), "+f"(oacc[mt][nt][1]),
                          "+f"(oacc[mt][nt][2]), "+f"(oacc[mt][nt][3])
                        : "r"(af[mt][0]), "r"(af[mt][1]), "r"(af[mt][2]), "r"(af[mt][3]),
                          "r"(bf[nt][0]), "r"(bf[nt][1]));
                }
        }
        __syncthreads();
    }

    // ---- finalize: divide by l, write image-order output ----
    float linv[4];
    #pragma unroll
    for (int g = 0; g < 4; g++) linv[g] = 1.0f / lrun[g];

    int jj = p / 7, ii = p % 7;
    #pragma unroll
    for (int mt = 0; mt < 2; mt++) {
        #pragma unroll
        for (int half = 0; half < 2; half++) {
            int q = warp * 32 + mt * 16 + qr + half * 8;
            int y = jj * 8 + (q >> 3), x = ii * 8 + (q & 7);
            float* orow = O + ((size_t)(n * HWDIM + y) * HWDIM + x) * CDIM + mh * 32;
            float li = linv[mt * 2 + half];
            #pragma unroll
            for (int nt = 0; nt < 4; nt++) {
                float2 v;
                v.x = oacc[mt][nt][half * 2 + 0] * li;
                v.y = oacc[mt][nt][half * 2 + 1] * li;
                *(float2*)(orow + nt * 8 + qc * 2) = v;
            }
        }
    }
}

// ---------------- 5x5 depthwise lepe, smem-tiled, accumulates into O ----------------
// grid (392 windows, 4 channel groups of 64), 256 threads
__global__ __launch_bounds__(256)
void lepe_kernel(const float* __restrict__ QKV, const float* __restrict__ W,
                 const float* __restrict__ B, float* __restrict__ O) {
    __shared__ float sv[144][64];   // 12x12 halo tile x 64 channels
    __shared__ float sw[25][64];
    int np = blockIdx.x, cg = blockIdx.y;
    int n = np / NWIN, p = np % NWIN;
    int jj = p / 7, ii = p % 7;
    int tid = threadIdx.x;

    for (int i = tid; i < 1600; i += 256)
        sw[i / 64][i % 64] = W[(i / 64) * CDIM + cg * 64 + (i % 64)];

    for (int i = tid; i < 2304; i += 256) {
        int pos = i >> 4, c4 = i & 15;
        int yy = jj * 8 + (pos / 12) - 2;
        int xx = ii * 8 + (pos % 12) - 2;
        float4 v = make_float4(0.f, 0.f, 0.f, 0.f);
        if (yy >= 0 && yy < HWDIM && xx >= 0 && xx < HWDIM) {
            int pp = (yy >> 3) * 7 + (xx >> 3);
            int qi = (yy & 7) * 8 + (xx & 7);
            const float* src = QKV + ((size_t)(n * NWIN + pp) * 64 + qi) * QKC + 512 + cg * 64;
            v = *(const float4*)(src + c4 * 4);
        }
        *(float4*)&sv[pos][c4 * 4] = v;
    }
    __syncthreads();

    int c = tid & 63, pp0 = tid >> 6;    // pp0 in 0..3
    float wr[25];
    #pragma unroll
    for (int t5 = 0; t5 < 25; t5++) wr[t5] = sw[t5][c];
    float bias = B[cg * 64 + c];

    #pragma unroll
    for (int hi = 0; hi < 2; hi++) {
        int hh = pp0 + hi * 4;
        #pragma unroll
        for (int ww = 0; ww < 8; ww++) {
            float acc = bias;
            #pragma unroll
            for (int dy = 0; dy < 5; dy++)
                #pragma unroll
                for (int dx = 0; dx < 5; dx++)
                    acc += sv[(hh + dy) * 12 + (ww + dx)][c] * wr[dy * 5 + dx];
            int y = jj * 8 + hh, x = ii * 8 + ww;
            int t = (n * HWDIM + y) * HWDIM + x;
            O[(size_t)t * CDIM + cg * 64 + c] += acc;
        }
    }
}

// ---------------- host launch ----------------
extern "C" void kernel_launch(void* const* d_in, const int* in_sizes, int n_in,
                              void* d_out, int out_size) {
    const float* x      = (const float*)d_in[0];
    const float* ln1_g  = (const float*)d_in[1];
    const float* ln1_b  = (const float*)d_in[2];
    const float* qkv_w  = (const float*)d_in[3];
    const float* qkv_b  = (const float*)d_in[4];
    const float* lepe_w = (const float*)d_in[5];
    const float* lepe_b = (const float*)d_in[6];
    const float* wo_w   = (const float*)d_in[7];
    const float* wo_b   = (const float*)d_in[8];
    const float* ln2_g  = (const float*)d_in[9];
    const float* ln2_b  = (const float*)d_in[10];
    const float* mlp_w1 = (const float*)d_in[11];
    const float* mlp_b1 = (const float*)d_in[12];
    const float* mlp_w2 = (const float*)d_in[13];
    const float* mlp_b2 = (const float*)d_in[14];
    float* out = (float*)d_out;

    float *tmp, *qkv, *x1, *hid, *qw, *kw;
    int* tk;
    cudaGetSymbolAddress((void**)&tmp, g_tmp256);
    cudaGetSymbolAddress((void**)&qkv, g_qkv);
    cudaGetSymbolAddress((void**)&x1,  g_x1);
    cudaGetSymbolAddress((void**)&hid, g_hid);
    cudaGetSymbolAddress((void**)&qw,  g_qwin);
    cudaGetSymbolAddress((void**)&kw,  g_kwin);
    cudaGetSymbolAddress((void**)&tk,  g_topk);

    // 1. LN1 with window permute (image -> windowed token order)
    ln_kernel<true><<<TOK / 8, 256>>>(x, ln1_g, ln1_b, tmp);
    // 2. qkv GEMM: [25088,256] x [256,768]
    tgemm_kernel<0><<<dim3(QKC / 128, TOK / 128), 256>>>(tmp, qkv_w, qkv_b, nullptr, qkv,
                                                         TOK, QKC, CDIM);
    // 3. window means
    winmean_kernel<<<NPALL, 256>>>(qkv, qw, kw);
    // 4. router + top-4
    router_kernel<<<NPALL, 256>>>(qw, kw, tk);
    // 5. gathered attention (tensor cores; writes image order into tmp)
    attn_kernel<<<dim3(NPALL, 8), 64>>>(qkv, tk, tmp);
    // 6. lepe depthwise conv accumulates into tmp
    lepe_kernel<<<dim3(NPALL, 4), 256>>>(qkv, lepe_w, lepe_b, tmp);
    // 7. wo GEMM + residual with original x -> x1
    tgemm_kernel<2><<<dim3(CDIM / 128, TOK / 128), 256>>>(tmp, wo_w, wo_b, x, x1,
                                                          TOK, CDIM, CDIM);
    // 8. LN2 (no permute)
    ln_kernel<false><<<TOK / 8, 256>>>(x1, ln2_g, ln2_b, tmp);
    // 9. MLP1 + exact GELU
    tgemm_kernel<1><<<dim3(HIDC / 128, TOK / 128), 256>>>(tmp, mlp_w1, mlp_b1, nullptr, hid,
                                                          TOK, HIDC, CDIM);
    // 10. MLP2 + residual -> out
    tgemm_kernel<2><<<dim3(CDIM / 128, TOK / 128), 256>>>(hid, mlp_w2, mlp_b2, x1, out,
                                                          TOK, CDIM, HIDC);
}

// round 7
// speedup vs baseline: 3.4619x; 1.2421x over previous
#include <cuda_runtime.h>
#include <cuda_bf16.h>
#include <math.h>
#include <stdint.h>

// ---------------- problem constants ----------------
#define TOK    25088      // 8*56*56
#define NBATCH 8
#define HWDIM  56
#define CDIM   256
#define QKC    768        // qkv width
#define HIDC   1024
#define NWIN   49         // 7*7 windows per image
#define NPALL  392        // 8*49
#define WSCALE 0.0625f    // 256^-0.5

// ---------------- scratch (device globals; no allocs allowed) ----------------
__device__ float g_tmp256[TOK * CDIM];     // ln1(win-order) -> attn+lepe(img) -> ln2
__device__ float g_qkv[TOK * QKC];         // windowed token order
__device__ float g_x1[TOK * CDIM];         // after first residual
__device__ float g_hid[(size_t)TOK * HIDC];
__device__ float g_qwin[NPALL * CDIM];
__device__ float g_kwin[NPALL * CDIM];
__device__ int   g_topk[NPALL * 4];
__device__ __nv_bfloat16 g_wbf[786432];    // transposed bf16 weights

#define WT_QKV 0
#define WT_WO  196608
#define WT_W1  262144
#define WT_W2  524288

__device__ __forceinline__ uint32_t f2tf32(float x) {
    uint32_t u;
    asm("cvt.rna.tf32.f32 %0, %1;" : "=r"(u) : "f"(x));
    return u;
}
__device__ __forceinline__ float tf32f(float x) { return __uint_as_float(f2tf32(x)); }

__device__ __forceinline__ uint32_t packbf2(float x, float y) {
    __nv_bfloat162 b = __floats2bfloat162_rn(x, y);
    return *(uint32_t*)&b;
}

// ---------------- weight transpose + bf16 convert: W[K][N] -> WT[N][K] ----------------
__global__ void wtrans_kernel(const float* __restrict__ W, __nv_bfloat16* __restrict__ WT,
                              int K, int N) {
    __shared__ float tile[32][33];
    int k0 = blockIdx.x * 32, n0 = blockIdx.y * 32;
    int tx = threadIdx.x & 31, ty = threadIdx.x >> 5;   // 32 x 8
    #pragma unroll
    for (int i = ty; i < 32; i += 8)
        tile[i][tx] = W[(size_t)(k0 + i) * N + n0 + tx];
    __syncthreads();
    #pragma unroll
    for (int i = ty; i < 32; i += 8)
        WT[(size_t)(n0 + i) * K + k0 + tx] = __float2bfloat16(tile[tx][i]);
}

// ---------------- LayerNorm (warp per token), optional window permute ----------------
template<bool PERM>
__global__ void ln_kernel(const float* __restrict__ X, const float* __restrict__ gam,
                          const float* __restrict__ bet, float* __restrict__ Y) {
    int warp = threadIdx.x >> 5, lane = threadIdx.x & 31;
    int t = blockIdx.x * 8 + warp;
    const float* row = X + (size_t)t * CDIM;
    float4 v0 = *(const float4*)(row + lane * 8);
    float4 v1 = *(const float4*)(row + lane * 8 + 4);
    float s  = v0.x + v0.y + v0.z + v0.w + v1.x + v1.y + v1.z + v1.w;
    float sq = v0.x*v0.x + v0.y*v0.y + v0.z*v0.z + v0.w*v0.w
             + v1.x*v1.x + v1.y*v1.y + v1.z*v1.z + v1.w*v1.w;
    #pragma unroll
    for (int o = 16; o; o >>= 1) {
        s  += __shfl_xor_sync(0xffffffffu, s, o);
        sq += __shfl_xor_sync(0xffffffffu, sq, o);
    }
    float mu  = s * (1.0f / 256.0f);
    float var = sq * (1.0f / 256.0f) - mu * mu;
    float inv = rsqrtf(var + 1e-6f);

    int orow;
    if (PERM) {
        int n = t / 3136, rem = t % 3136;
        int y = rem / 56, x = rem % 56;
        int p  = (y >> 3) * 7 + (x >> 3);
        int qi = (y & 7) * 8 + (x & 7);
        orow = (n * NWIN + p) * 64 + qi;
    } else {
        orow = t;
    }
    float4 g0 = *(const float4*)(gam + lane * 8);
    float4 g1 = *(const float4*)(gam + lane * 8 + 4);
    float4 b0 = *(const float4*)(bet + lane * 8);
    float4 b1 = *(const float4*)(bet + lane * 8 + 4);
    float4 o0, o1;
    o0.x = (v0.x - mu) * inv * g0.x + b0.x;
    o0.y = (v0.y - mu) * inv * g0.y + b0.y;
    o0.z = (v0.z - mu) * inv * g0.z + b0.z;
    o0.w = (v0.w - mu) * inv * g0.w + b0.w;
    o1.x = (v1.x - mu) * inv * g1.x + b1.x;
    o1.y = (v1.y - mu) * inv * g1.y + b1.y;
    o1.z = (v1.z - mu) * inv * g1.z + b1.z;
    o1.w = (v1.w - mu) * inv * g1.w + b1.w;
    float* orp = Y + (size_t)orow * CDIM + lane * 8;
    *(float4*)(orp)     = o0;
    *(float4*)(orp + 4) = o1;
}

// ---------------- BF16 tensor-core GEMM 128x128x32, 256 threads ----------------
// A fp32 [M][K] (converted on stage), B = WT bf16 [N][K]. fp32 accumulate.
// 8 warps 2(m) x 4(n); warp: 64x32 via 4x4 m16n8k16 tiles.
__device__ __forceinline__ float gelu_exact(float x) {
    return 0.5f * x * (1.0f + erff(x * 0.70710678118654752440f));
}

#define WPAD 20   // row stride in 32-bit words (bf16 pairs); 16 data words + 4 pad

template<int EPI>
__global__ __launch_bounds__(256)
void tgemm_kernel(const float* __restrict__ A, const __nv_bfloat16* __restrict__ WT,
                  const float* __restrict__ bias, const float* __restrict__ R,
                  float* __restrict__ C, int M, int N, int K) {
    __shared__ uint32_t sA[2][128 * WPAD];   // [m][k-pair]
    __shared__ uint32_t sB[2][128 * WPAD];   // [n][k-pair]

    int tid = threadIdx.x;
    int warp = tid >> 5, lane = tid & 31;
    int qr = lane >> 2, qc = lane & 3;
    int warp_m = warp >> 2, warp_n = warp & 3;   // 2 x 4
    int m0 = blockIdx.y * 128, n0 = blockIdx.x * 128;

    int aRow = tid >> 1;
    int half = tid & 1;                 // covers k-halves of the 32-wide tile
    const float* Ag = A + (size_t)(m0 + aRow) * K + half * 16;
    const __nv_bfloat16* Bg = WT + (size_t)(n0 + aRow) * K + half * 16;
    int dstW = aRow * WPAD + half * 8;  // word offset

    float acc[4][4][4];
    #pragma unroll
    for (int i = 0; i < 4; i++)
        #pragma unroll
        for (int j = 0; j < 4; j++)
            #pragma unroll
            for (int v = 0; v < 4; v++) acc[i][j][v] = 0.0f;

    // prologue: k-tile 0 -> buffer 0
    {
        float4 a0 = *(const float4*)(Ag);
        float4 a1 = *(const float4*)(Ag + 4);
        float4 a2 = *(const float4*)(Ag + 8);
        float4 a3 = *(const float4*)(Ag + 12);
        uint4 w0, w1;
        w0.x = packbf2(a0.x, a0.y); w0.y = packbf2(a0.z, a0.w);
        w0.z = packbf2(a1.x, a1.y); w0.w = packbf2(a1.z, a1.w);
        w1.x = packbf2(a2.x, a2.y); w1.y = packbf2(a2.z, a2.w);
        w1.z = packbf2(a3.x, a3.y); w1.w = packbf2(a3.z, a3.w);
        *(uint4*)&sA[0][dstW]     = w0;
        *(uint4*)&sA[0][dstW + 4] = w1;
        uint4 b0 = *(const uint4*)(Bg);
        uint4 b1 = *(const uint4*)(Bg + 8);
        *(uint4*)&sB[0][dstW]     = b0;
        *(uint4*)&sB[0][dstW + 4] = b1;
    }
    __syncthreads();

    int p = 0;
    for (int k0 = 0; k0 < K; k0 += 32) {
        bool more = (k0 + 32) < K;
        float4 na0, na1, na2, na3;
        uint4 nb0, nb1;
        if (more) {
            na0 = *(const float4*)(Ag + k0 + 32);
            na1 = *(const float4*)(Ag + k0 + 36);
            na2 = *(const float4*)(Ag + k0 + 40);
            na3 = *(const float4*)(Ag + k0 + 44);
            nb0 = *(const uint4*)(Bg + k0 + 32);
            nb1 = *(const uint4*)(Bg + k0 + 40);
        }

        const uint32_t* Ab = sA[p];
        const uint32_t* Bb = sB[p];
        #pragma unroll
        for (int ksp = 0; ksp < 2; ksp++) {
            uint32_t af[4][4], bf[4][2];
            #pragma unroll
            for (int mt = 0; mt < 4; mt++) {
                int r = warp_m * 64 + mt * 16 + qr;
                af[mt][0] = Ab[(r)     * WPAD + ksp * 8 + qc];
                af[mt][1] = Ab[(r + 8) * WPAD + ksp * 8 + qc];
                af[mt][2] = Ab[(r)     * WPAD + ksp * 8 + qc + 4];
                af[mt][3] = Ab[(r + 8) * WPAD + ksp * 8 + qc + 4];
            }
            #pragma unroll
            for (int nt = 0; nt < 4; nt++) {
                int cn = warp_n * 32 + nt * 8 + qr;
                bf[nt][0] = Bb[cn * WPAD + ksp * 8 + qc];
                bf[nt][1] = Bb[cn * WPAD + ksp * 8 + qc + 4];
            }
            #pragma unroll
            for (int mt = 0; mt < 4; mt++)
                #pragma unroll
                for (int nt = 0; nt < 4; nt++) {
                    asm volatile(
                        "mma.sync.aligned.m16n8k16.row.col.f32.bf16.bf16.f32 "
                        "{%0,%1,%2,%3}, {%4,%5,%6,%7}, {%8,%9}, {%0,%1,%2,%3};"
                        : "+f"(acc[mt][nt][0]), "+f"(acc[mt][nt][1]),
                          "+f"(acc[mt][nt][2]), "+f"(acc[mt][nt][3])
                        : "r"(af[mt][0]), "r"(af[mt][1]), "r"(af[mt][2]), "r"(af[mt][3]),
                          "r"(bf[nt][0]), "r"(bf[nt][1]));
                }
        }

        if (more) {
            uint4 w0, w1;
            w0.x = packbf2(na0.x, na0.y); w0.y = packbf2(na0.z, na0.w);
            w0.z = packbf2(na1.x, na1.y); w0.w = packbf2(na1.z, na1.w);
            w1.x = packbf2(na2.x, na2.y); w1.y = packbf2(na2.z, na2.w);
            w1.z = packbf2(na3.x, na3.y); w1.w = packbf2(na3.z, na3.w);
            *(uint4*)&sA[p ^ 1][dstW]     = w0;
            *(uint4*)&sA[p ^ 1][dstW + 4] = w1;
            *(uint4*)&sB[p ^ 1][dstW]     = nb0;
            *(uint4*)&sB[p ^ 1][dstW + 4] = nb1;
        }
        __syncthreads();
        p ^= 1;
    }

    // epilogue: c0,c1 at (row, col..col+1), c2,c3 at (row+8, col..col+1)
    #pragma unroll
    for (int nt = 0; nt < 4; nt++) {
        int col = n0 + warp_n * 32 + nt * 8 + qc * 2;
        float bx = bias[col], by = bias[col + 1];
        #pragma unroll
        for (int mt = 0; mt < 4; mt++) {
            int row = m0 + warp_m * 64 + mt * 16 + qr;
            float v0 = acc[mt][nt][0] + bx;
            float v1 = acc[mt][nt][1] + by;
            float v2 = acc[mt][nt][2] + bx;
            float v3 = acc[mt][nt][3] + by;
            if (EPI == 1) {
                v0 = gelu_exact(v0); v1 = gelu_exact(v1);
                v2 = gelu_exact(v2); v3 = gelu_exact(v3);
            }
            if (EPI == 2) {
                const float* r0 = R + (size_t)row * N + col;
                const float* r1 = R + (size_t)(row + 8) * N + col;
                float2 ra = *(const float2*)r0;
                float2 rb = *(const float2*)r1;
                v0 += ra.x; v1 += ra.y; v2 += rb.x; v3 += rb.y;
            }
            float2 oa; oa.x = v0; oa.y = v1;
            float2 ob; ob.x = v2; ob.y = v3;
            *(float2*)(C + (size_t)row * N + col)       = oa;
            *(float2*)(C + (size_t)(row + 8) * N + col) = ob;
        }
    }
}

// ---------------- per-window mean of q and k ----------------
__global__ void winmean_kernel(const float* __restrict__ QKV,
                               float* __restrict__ qw, float* __restrict__ kw) {
    int np = blockIdx.x;           // 0..391
    int c = threadIdx.x;           // 0..255
    const float* base = QKV + (size_t)np * 64 * QKC;
    float sq = 0.f, sk = 0.f;
    #pragma unroll 8
    for (int t = 0; t < 64; t++) {
        sq += base[(size_t)t * QKC + c];
        sk += base[(size_t)t * QKC + 256 + c];
    }
    qw[np * CDIM + c] = sq * (1.0f / 64.0f);
    kw[np * CDIM + c] = sk * (1.0f / 64.0f);
}

// ---------------- router: warp-per-logit, coalesced + shfl reduce ----------------
__global__ void router_kernel(const float* __restrict__ qw, const float* __restrict__ kw,
                              int* __restrict__ topk) {
    int np = blockIdx.x;
    int n = np / NWIN;
    int tid = threadIdx.x;         // 256 threads = 8 warps
    int warp = tid >> 5, lane = tid & 31;
    __shared__ float qs[CDIM];
    __shared__ float lg[64];
    qs[tid] = qw[np * CDIM + tid] * WSCALE;
    __syncthreads();
    for (int q = warp; q < NWIN; q += 8) {
        const float* kr = kw + (size_t)(n * NWIN + q) * CDIM;
        float s = 0.f;
        #pragma unroll
        for (int h = 0; h < 2; h++) {
            float4 kv = ((const float4*)kr)[h * 32 + lane];
            float4 qv = ((const float4*)qs)[h * 32 + lane];
            s += kv.x * qv.x + kv.y * qv.y + kv.z * qv.z + kv.w * qv.w;
        }
        #pragma unroll
        for (int o = 16; o; o >>= 1) s += __shfl_xor_sync(0xffffffffu, s, o);
        if (lane == 0) lg[q] = s;
    }
    __syncthreads();
    if (tid == 0) {
        bool used[NWIN];
        #pragma unroll
        for (int i = 0; i < NWIN; i++) used[i] = false;
        for (int r = 0; r < 4; r++) {
            float best = -1e30f; int bi = 0;
            for (int q = 0; q < NWIN; q++)
                if (!used[q] && lg[q] > best) { best = lg[q]; bi = q; }
            used[bi] = true;
            topk[np * 4 + r] = bi;
        }
    }
}

// ---------------- tensor-core gathered attention (TF32 mma), online softmax ----------
// grid (392, 8 heads), 64 threads = 2 warps; warp w owns query rows [w*32, w*32+32)
#define KS_STRIDE 36
#define VS_STRIDE 40
#define PS_STRIDE 68
__global__ __launch_bounds__(64)
void attn_kernel(const float* __restrict__ QKV, const int* __restrict__ topk,
                 float* __restrict__ O) {
    __shared__ float ks[64][KS_STRIDE];
    __shared__ float vs[64][VS_STRIDE];
    __shared__ float ps[64][PS_STRIDE];   // Q stage first, then per-warp P (warp w: rows w*32..)

    int np = blockIdx.x, mh = blockIdx.y;
    int n = np / NWIN, p = np % NWIN;
    int tid = threadIdx.x, warp = tid >> 5, lane = tid & 31;
    int qr = lane >> 2, qc = lane & 3;

    // ---- stage Q (64 x 32), scaled + tf32-rounded ----
    const float* qbase = QKV + (size_t)np * 64 * QKC + mh * 32;
    for (int i = tid; i < 512; i += 64) {
        int r = i >> 3, c = (i & 7) * 4;
        float4 v = *(const float4*)(qbase + (size_t)r * QKC + c);
        ps[r][c + 0] = tf32f(v.x * WSCALE);
        ps[r][c + 1] = tf32f(v.y * WSCALE);
        ps[r][c + 2] = tf32f(v.z * WSCALE);
        ps[r][c + 3] = tf32f(v.w * WSCALE);
    }
    __syncthreads();

    // ---- preload Q fragments ----
    uint32_t qf[2][4][4];
    #pragma unroll
    for (int mt = 0; mt < 2; mt++) {
        int r = warp * 32 + mt * 16 + qr;
        #pragma unroll
        for (int kk = 0; kk < 4; kk++) {
            qf[mt][kk][0] = __float_as_uint(ps[r][kk * 8 + qc]);
            qf[mt][kk][1] = __float_as_uint(ps[r + 8][kk * 8 + qc]);
            qf[mt][kk][2] = __float_as_uint(ps[r][kk * 8 + qc + 4]);
            qf[mt][kk][3] = __float_as_uint(ps[r + 8][kk * 8 + qc + 4]);
        }
    }
    __syncthreads();   // ps will be reused for P

    float mrun[4] = {-1e30f, -1e30f, -1e30f, -1e30f};
    float lrun[4] = {0.f, 0.f, 0.f, 0.f};
    float oacc[2][4][4];
    #pragma unroll
    for (int mt = 0; mt < 2; mt++)
        #pragma unroll
        for (int nt = 0; nt < 4; nt++)
            #pragma unroll
            for (int v = 0; v < 4; v++) oacc[mt][nt][v] = 0.f;

    for (int t4 = 0; t4 < 4; t4++) {
        int rwin = topk[np * 4 + t4];
        const float* kb = QKV + (size_t)(n * NWIN + rwin) * 64 * QKC + 256 + mh * 32;
        for (int i = tid; i < 512; i += 64) {
            int r = i >> 3, c = (i & 7) * 4;
            float4 kv = *(const float4*)(kb + (size_t)r * QKC + c);
            ks[r][c + 0] = tf32f(kv.x); ks[r][c + 1] = tf32f(kv.y);
            ks[r][c + 2] = tf32f(kv.z); ks[r][c + 3] = tf32f(kv.w);
            float4 vv = *(const float4*)(kb + (size_t)r * QKC + 256 + c);
            vs[r][c + 0] = tf32f(vv.x); vs[r][c + 1] = tf32f(vv.y);
            vs[r][c + 2] = tf32f(vv.z); vs[r][c + 3] = tf32f(vv.w);
        }
        __syncthreads();

        float sacc[2][8][4];
        #pragma unroll
        for (int mt = 0; mt < 2; mt++)
            #pragma unroll
            for (int nt = 0; nt < 8; nt++)
                #pragma unroll
                for (int v = 0; v < 4; v++) sacc[mt][nt][v] = 0.f;

        #pragma unroll
        for (int kk = 0; kk < 4; kk++) {
            uint32_t bf[8][2];
            #pragma unroll
            for (int nt = 0; nt < 8; nt++) {
                bf[nt][0] = __float_as_uint(ks[nt * 8 + qr][kk * 8 + qc]);
                bf[nt][1] = __float_as_uint(ks[nt * 8 + qr][kk * 8 + qc + 4]);
            }
            #pragma unroll
            for (int mt = 0; mt < 2; mt++)
                #pragma unroll
                for (int nt = 0; nt < 8; nt++) {
                    asm volatile(
                        "mma.sync.aligned.m16n8k8.row.col.f32.tf32.tf32.f32 "
                        "{%0,%1,%2,%3}, {%4,%5,%6,%7}, {%8,%9}, {%0,%1,%2,%3};"
                        : "+f"(sacc[mt][nt][0]), "+f"(sacc[mt][nt][1]),
                          "+f"(sacc[mt][nt][2]), "+f"(sacc[mt][nt][3])
                        : "r"(qf[mt][kk][0]), "r"(qf[mt][kk][1]),
                          "r"(qf[mt][kk][2]), "r"(qf[mt][kk][3]),
                          "r"(bf[nt][0]), "r"(bf[nt][1]));
                }
        }

        float rmax[4] = {-1e30f, -1e30f, -1e30f, -1e30f};
        #pragma unroll
        for (int mt = 0; mt < 2; mt++)
            #pragma unroll
            for (int nt = 0; nt < 8; nt++) {
                rmax[mt * 2 + 0] = fmaxf(rmax[mt * 2 + 0], fmaxf(sacc[mt][nt][0], sacc[mt][nt][1]));
                rmax[mt * 2 + 1] = fmaxf(rmax[mt * 2 + 1], fmaxf(sacc[mt][nt][2], sacc[mt][nt][3]));
            }
        #pragma unroll
        for (int g = 0; g < 4; g++) {
            rmax[g] = fmaxf(rmax[g], __shfl_xor_sync(0xffffffffu, rmax[g], 1));
            rmax[g] = fmaxf(rmax[g], __shfl_xor_sync(0xffffffffu, rmax[g], 2));
        }
        float corr[4], mnew[4];
        #pragma unroll
        for (int g = 0; g < 4; g++) {
            mnew[g] = fmaxf(mrun[g], rmax[g]);
            corr[g] = __expf(mrun[g] - mnew[g]);
            lrun[g] *= corr[g];
            mrun[g] = mnew[g];
        }
        #pragma unroll
        for (int mt = 0; mt < 2; mt++)
            #pragma unroll
            for (int nt = 0; nt < 4; nt++) {
                oacc[mt][nt][0] *= corr[mt * 2 + 0];
                oacc[mt][nt][1] *= corr[mt * 2 + 0];
                oacc[mt][nt][2] *= corr[mt * 2 + 1];
                oacc[mt][nt][3] *= corr[mt * 2 + 1];
            }
        float psum[4] = {0.f, 0.f, 0.f, 0.f};
        #pragma unroll
        for (int mt = 0; mt < 2; mt++) {
            int r0 = warp * 32 + mt * 16 + qr;
            #pragma unroll
            for (int nt = 0; nt < 8; nt++) {
                float p0 = __expf(sacc[mt][nt][0] - mnew[mt * 2 + 0]);
                float p1 = __expf(sacc[mt][nt][1] - mnew[mt * 2 + 0]);
                float p2 = __expf(sacc[mt][nt][2] - mnew[mt * 2 + 1]);
                float p3 = __expf(sacc[mt][nt][3] - mnew[mt * 2 + 1]);
                psum[mt * 2 + 0] += p0 + p1;
                psum[mt * 2 + 1] += p2 + p3;
                float2 w0; w0.x = tf32f(p0); w0.y = tf32f(p1);
                float2 w1; w1.x = tf32f(p2); w1.y = tf32f(p3);
                *(float2*)&ps[r0][nt * 8 + qc * 2]     = w0;
                *(float2*)&ps[r0 + 8][nt * 8 + qc * 2] = w1;
            }
        }
        #pragma unroll
        for (int g = 0; g < 4; g++) {
            psum[g] += __shfl_xor_sync(0xffffffffu, psum[g], 1);
            psum[g] += __shfl_xor_sync(0xffffffffu, psum[g], 2);
            lrun[g] += psum[g];
        }
        __syncwarp();

        #pragma unroll
        for (int kt = 0; kt < 8; kt++) {
            uint32_t af[2][4], bf[4][2];
            #pragma unroll
            for (int mt = 0; mt < 2; mt++) {
                int r = warp * 32 + mt * 16 + qr;
                af[mt][0] = __float_as_uint(ps[r][kt * 8 + qc]);
                af[mt][1] = __float_as_uint(ps[r + 8][kt * 8 + qc]);
                af[mt][2] = __float_as_uint(ps[r][kt * 8 + qc + 4]);
                af[mt][3] = __float_as_uint(ps[r + 8][kt * 8 + qc + 4]);
            }
            #pragma unroll
            for (int nt = 0; nt < 4; nt++) {
                bf[nt][0] = __float_as_uint(vs[kt * 8 + qc][nt * 8 + qr]);
                bf[nt][1] = __float_as_uint(vs[kt * 8 + qc + 4][nt * 8 + qr]);
            }
            #pragma unroll
            for (int mt = 0; mt < 2; mt++)
                #pragma unroll
                for (int nt = 0; nt < 4; nt++) {
                    asm volatile(
                        "mma.sync.aligned.m16n8k8.row.col.f32.tf32.tf32.f32 "
                        "{%0,%1,%2,%3}, {%4,%5,%6,%7}, {%8,%9}, {%0,%1,%2,%3};"
                        : "+f"(oacc[mt][nt][0]), "+f"(oacc[mt][nt][1]),
                          "+f"(oacc[mt][nt][2]), "+f"(oacc[mt][nt][3])
                        : "r"(af[mt][0]), "r"(af[mt][1]), "r"(af[mt][2]), "r"(af[mt][3]),
                          "r"(bf[nt][0]), "r"(bf[nt][1]));
                }
        }
        __syncthreads();
    }

    float linv[4];
    #pragma unroll
    for (int g = 0; g < 4; g++) linv[g] = 1.0f / lrun[g];

    int jj = p / 7, ii = p % 7;
    #pragma unroll
    for (int mt = 0; mt < 2; mt++) {
        #pragma unroll
        for (int half = 0; half < 2; half++) {
            int q = warp * 32 + mt * 16 + qr + half * 8;
            int y = jj * 8 + (q >> 3), x = ii * 8 + (q & 7);
            float* orow = O + ((size_t)(n * HWDIM + y) * HWDIM + x) * CDIM + mh * 32;
            float li = linv[mt * 2 + half];
            #pragma unroll
            for (int nt = 0; nt < 4; nt++) {
                float2 v;
                v.x = oacc[mt][nt][half * 2 + 0] * li;
                v.y = oacc[mt][nt][half * 2 + 1] * li;
                *(float2*)(orow + nt * 8 + qc * 2) = v;
            }
        }
    }
}

// ---------------- 5x5 depthwise lepe, smem-tiled, accumulates into O ----------------
__global__ __launch_bounds__(256)
void lepe_kernel(const float* __restrict__ QKV, const float* __restrict__ W,
                 const float* __restrict__ B, float* __restrict__ O) {
    __shared__ float sv[144][64];   // 12x12 halo tile x 64 channels
    __shared__ float sw[25][64];
    int np = blockIdx.x, cg = blockIdx.y;
    int n = np / NWIN, p = np % NWIN;
    int jj = p / 7, ii = p % 7;
    int tid = threadIdx.x;

    for (int i = tid; i < 1600; i += 256)
        sw[i / 64][i % 64] = W[(i / 64) * CDIM + cg * 64 + (i % 64)];

    for (int i = tid; i < 2304; i += 256) {
        int pos = i >> 4, c4 = i & 15;
        int yy = jj * 8 + (pos / 12) - 2;
        int xx = ii * 8 + (pos % 12) - 2;
        float4 v = make_float4(0.f, 0.f, 0.f, 0.f);
        if (yy >= 0 && yy < HWDIM && xx >= 0 && xx < HWDIM) {
            int pp = (yy >> 3) * 7 + (xx >> 3);
            int qi = (yy & 7) * 8 + (xx & 7);
            const float* src = QKV + ((size_t)(n * NWIN + pp) * 64 + qi) * QKC + 512 + cg * 64;
            v = *(const float4*)(src + c4 * 4);
        }
        *(float4*)&sv[pos][c4 * 4] = v;
    }
    __syncthreads();

    int c = tid & 63, pp0 = tid >> 6;    // pp0 in 0..3
    float wr[25];
    #pragma unroll
    for (int t5 = 0; t5 < 25; t5++) wr[t5] = sw[t5][c];
    float bias = B[cg * 64 + c];

    #pragma unroll
    for (int hi = 0; hi < 2; hi++) {
        int hh = pp0 + hi * 4;
        #pragma unroll
        for (int ww = 0; ww < 8; ww++) {
            float acc = bias;
            #pragma unroll
            for (int dy = 0; dy < 5; dy++)
                #pragma unroll
                for (int dx = 0; dx < 5; dx++)
                    acc += sv[(hh + dy) * 12 + (ww + dx)][c] * wr[dy * 5 + dx];
            int y = jj * 8 + hh, x = ii * 8 + ww;
            int t = (n * HWDIM + y) * HWDIM + x;
            O[(size_t)t * CDIM + cg * 64 + c] += acc;
        }
    }
}

// ---------------- host launch ----------------
extern "C" void kernel_launch(void* const* d_in, const int* in_sizes, int n_in,
                              void* d_out, int out_size) {
    const float* x      = (const float*)d_in[0];
    const float* ln1_g  = (const float*)d_in[1];
    const float* ln1_b  = (const float*)d_in[2];
    const float* qkv_w  = (const float*)d_in[3];
    const float* qkv_b  = (const float*)d_in[4];
    const float* lepe_w = (const float*)d_in[5];
    const float* lepe_b = (const float*)d_in[6];
    const float* wo_w   = (const float*)d_in[7];
    const float* wo_b   = (const float*)d_in[8];
    const float* ln2_g  = (const float*)d_in[9];
    const float* ln2_b  = (const float*)d_in[10];
    const float* mlp_w1 = (const float*)d_in[11];
    const float* mlp_b1 = (const float*)d_in[12];
    const float* mlp_w2 = (const float*)d_in[13];
    const float* mlp_b2 = (const float*)d_in[14];
    float* out = (float*)d_out;

    float *tmp, *qkv, *x1, *hid, *qw, *kw;
    int* tk;
    __nv_bfloat16* wbf;
    cudaGetSymbolAddress((void**)&tmp, g_tmp256);
    cudaGetSymbolAddress((void**)&qkv, g_qkv);
    cudaGetSymbolAddress((void**)&x1,  g_x1);
    cudaGetSymbolAddress((void**)&hid, g_hid);
    cudaGetSymbolAddress((void**)&qw,  g_qwin);
    cudaGetSymbolAddress((void**)&kw,  g_kwin);
    cudaGetSymbolAddress((void**)&tk,  g_topk);
    cudaGetSymbolAddress((void**)&wbf, g_wbf);

    // 0. transpose + bf16-convert weights
    wtrans_kernel<<<dim3(CDIM / 32, QKC / 32), 256>>>(qkv_w,  wbf + WT_QKV, CDIM, QKC);
    wtrans_kernel<<<dim3(CDIM / 32, CDIM / 32), 256>>>(wo_w,  wbf + WT_WO,  CDIM, CDIM);
    wtrans_kernel<<<dim3(CDIM / 32, HIDC / 32), 256>>>(mlp_w1, wbf + WT_W1, CDIM, HIDC);
    wtrans_kernel<<<dim3(HIDC / 32, CDIM / 32), 256>>>(mlp_w2, wbf + WT_W2, HIDC, CDIM);

    // 1. LN1 with window permute (image -> windowed token order)
    ln_kernel<true><<<TOK / 8, 256>>>(x, ln1_g, ln1_b, tmp);
    // 2. qkv GEMM: [25088,256] x [256,768]
    tgemm_kernel<0><<<dim3(QKC / 128, TOK / 128), 256>>>(tmp, wbf + WT_QKV, qkv_b, nullptr,
                                                         qkv, TOK, QKC, CDIM);
    // 3. window means
    winmean_kernel<<<NPALL, 256>>>(qkv, qw, kw);
    // 4. router + top-4
    router_kernel<<<NPALL, 256>>>(qw, kw, tk);
    // 5. gathered attention (tensor cores; writes image order into tmp)
    attn_kernel<<<dim3(NPALL, 8), 64>>>(qkv, tk, tmp);
    // 6. lepe depthwise conv accumulates into tmp
    lepe_kernel<<<dim3(NPALL, 4), 256>>>(qkv, lepe_w, lepe_b, tmp);
    // 7. wo GEMM + residual with original x -> x1
    tgemm_kernel<2><<<dim3(CDIM / 128, TOK / 128), 256>>>(tmp, wbf + WT_WO, wo_b, x, x1,
                                                          TOK, CDIM, CDIM);
    // 8. LN2 (no permute)
    ln_kernel<false><<<TOK / 8, 256>>>(x1, ln2_g, ln2_b, tmp);
    // 9. MLP1 + exact GELU
    tgemm_kernel<1><<<dim3(HIDC / 128, TOK / 128), 256>>>(tmp, wbf + WT_W1, mlp_b1, nullptr,
                                                          hid, TOK, HIDC, CDIM);
    // 10. MLP2 + residual -> out
    tgemm_kernel<2><<<dim3(CDIM / 128, TOK / 128), 256>>>(hid, wbf + WT_W2, mlp_b2, x1, out,
                                                          TOK, CDIM, HIDC);
}

// round 10
// speedup vs baseline: 4.1026x; 1.1851x over previous
#include <cuda_runtime.h>
#include <cuda_bf16.h>
#include <math.h>
#include <stdint.h>

// ---------------- problem constants ----------------
#define TOK    25088      // 8*56*56
#define NBATCH 8
#define HWDIM  56
#define CDIM   256
#define QKC    768        // qkv width
#define HIDC   1024
#define NWIN   49         // 7*7 windows per image
#define NPALL  392        // 8*49
#define WSCALE 0.0625f    // 256^-0.5

// ---------------- scratch (device globals; no allocs allowed) ----------------
__device__ __align__(256) float g_tmp256[TOK * CDIM];   // ln1(bf16) -> attn+lepe(f32) -> ln2(bf16)
__device__ __align__(256) float g_qkv[TOK * QKC];
__device__ __align__(256) float g_x1[TOK * CDIM];
__device__ __align__(256) float g_hid[(size_t)TOK * HIDC / 2];  // bf16 storage
__device__ float g_qwin[NPALL * CDIM];
__device__ float g_kwin[NPALL * CDIM];
__device__ int   g_topk[NPALL * 4];
__device__ __align__(256) __nv_bfloat16 g_wbf[786432];  // transposed bf16 weights

#define WT_QKV 0
#define WT_WO  196608
#define WT_W1  262144
#define WT_W2  524288

__device__ __forceinline__ uint32_t f2tf32(float x) {
    uint32_t u;
    asm("cvt.rna.tf32.f32 %0, %1;" : "=r"(u) : "f"(x));
    return u;
}
__device__ __forceinline__ float tf32f(float x) { return __uint_as_float(f2tf32(x)); }

__device__ __forceinline__ uint32_t smem_u32(const void* p) {
    uint32_t a;
    asm("{ .reg .u64 t; cvta.to.shared.u64 t, %1; cvt.u32.u64 %0, t; }" : "=r"(a) : "l"(p));
    return a;
}
__device__ __forceinline__ void cpasync16(uint32_t s, const void* g) {
    asm volatile("cp.async.cg.shared.global [%0], [%1], 16;" :: "r"(s), "l"(g) : "memory");
}
#define CP_COMMIT() asm volatile("cp.async.commit_group;" ::: "memory")
#define CP_WAIT0()  asm volatile("cp.async.wait_group 0;" ::: "memory")

// ---------------- weight transpose + bf16 convert: W[K][N] -> WT[N][K] ----------------
__global__ void wtrans_kernel(const float* __restrict__ W, __nv_bfloat16* __restrict__ WT,
                              int K, int N) {
    __shared__ float tile[32][33];
    int k0 = blockIdx.x * 32, n0 = blockIdx.y * 32;
    int tx = threadIdx.x & 31, ty = threadIdx.x >> 5;   // 32 x 8
    #pragma unroll
    for (int i = ty; i < 32; i += 8)
        tile[i][tx] = W[(size_t)(k0 + i) * N + n0 + tx];
    __syncthreads();
    #pragma unroll
    for (int i = ty; i < 32; i += 8)
        WT[(size_t)(n0 + i) * K + k0 + tx] = __float2bfloat16(tile[tx][i]);
}

// ---------------- LayerNorm (warp per token) -> bf16 out, optional window permute ----
template<bool PERM>
__global__ void ln_kernel(const float* __restrict__ X, const float* __restrict__ gam,
                          const float* __restrict__ bet, __nv_bfloat16* __restrict__ Y) {
    int warp = threadIdx.x >> 5, lane = threadIdx.x & 31;
    int t = blockIdx.x * 8 + warp;
    const float* row = X + (size_t)t * CDIM;
    float4 v0 = *(const float4*)(row + lane * 8);
    float4 v1 = *(const float4*)(row + lane * 8 + 4);
    float s  = v0.x + v0.y + v0.z + v0.w + v1.x + v1.y + v1.z + v1.w;
    float sq = v0.x*v0.x + v0.y*v0.y + v0.z*v0.z + v0.w*v0.w
             + v1.x*v1.x + v1.y*v1.y + v1.z*v1.z + v1.w*v1.w;
    #pragma unroll
    for (int o = 16; o; o >>= 1) {
        s  += __shfl_xor_sync(0xffffffffu, s, o);
        sq += __shfl_xor_sync(0xffffffffu, sq, o);
    }
    float mu  = s * (1.0f / 256.0f);
    float var = sq * (1.0f / 256.0f) - mu * mu;
    float inv = rsqrtf(var + 1e-6f);

    int orow;
    if (PERM) {
        int n = t / 3136, rem = t % 3136;
        int y = rem / 56, x = rem % 56;
        int p  = (y >> 3) * 7 + (x >> 3);
        int qi = (y & 7) * 8 + (x & 7);
        orow = (n * NWIN + p) * 64 + qi;
    } else {
        orow = t;
    }
    float4 g0 = *(const float4*)(gam + lane * 8);
    float4 g1 = *(const float4*)(gam + lane * 8 + 4);
    float4 b0 = *(const float4*)(bet + lane * 8);
    float4 b1 = *(const float4*)(bet + lane * 8 + 4);
    __nv_bfloat162 o0 = __floats2bfloat162_rn((v0.x - mu) * inv * g0.x + b0.x,
                                              (v0.y - mu) * inv * g0.y + b0.y);
    __nv_bfloat162 o1 = __floats2bfloat162_rn((v0.z - mu) * inv * g0.z + b0.z,
                                              (v0.w - mu) * inv * g0.w + b0.w);
    __nv_bfloat162 o2 = __floats2bfloat162_rn((v1.x - mu) * inv * g1.x + b1.x,
                                              (v1.y - mu) * inv * g1.y + b1.y);
    __nv_bfloat162 o3 = __floats2bfloat162_rn((v1.z - mu) * inv * g1.z + b1.z,
                                              (v1.w - mu) * inv * g1.w + b1.w);
    uint4 pk;
    pk.x = *(uint32_t*)&o0; pk.y = *(uint32_t*)&o1;
    pk.z = *(uint32_t*)&o2; pk.w = *(uint32_t*)&o3;
    *(uint4*)(Y + (size_t)orow * CDIM + lane * 8) = pk;
}

// ---------------- BF16 tensor-core GEMM 128x128x32, 256 threads, cp.async staged ------
// EPI: 0 bias, 1 bias+GELU (bf16 out), 2 bias+residual (fp32 out)
// ABF: A operand is bf16 [M][K] (pure cp.async) vs fp32 (ld+cvt+STS)
// DOMEAN: fused per-window column means into qw/kw (qkv GEMM only)
__device__ __forceinline__ float gelu_exact(float x) {
    return 0.5f * x * (1.0f + erff(x * 0.70710678118654752440f));
}

#define WPAD 20   // row stride in 32-bit words (bf16 pairs); 16 data + 4 pad

template<int EPI, int ABF, int DOMEAN>
__global__ __launch_bounds__(256)
void tgemm_kernel(const void* __restrict__ Ain, const __nv_bfloat16* __restrict__ WT,
                  const float* __restrict__ bias, const float* __restrict__ R,
                  void* __restrict__ Cout, float* __restrict__ qw, float* __restrict__ kw,
                  int M, int N, int K) {
    __shared__ uint32_t sA[2][128 * WPAD];
    __shared__ uint32_t sB[2][128 * WPAD];

    int tid = threadIdx.x;
    int warp = tid >> 5, lane = tid & 31;
    int qr = lane >> 2, qc = lane & 3;
    int warp_m = warp >> 2, warp_n = warp & 3;   // 2 x 4
    int m0 = blockIdx.y * 128, n0 = blockIdx.x * 128;

    int aRow = tid >> 1, half = tid & 1;
    const __nv_bfloat16* Bg = WT + (size_t)(n0 + aRow) * K + half * 16;
    const __nv_bfloat16* Agb = (const __nv_bfloat16*)Ain + (size_t)(m0 + aRow) * K + half * 16;
    const float*         Agf = (const float*)Ain + (size_t)(m0 + aRow) * K + half * 16;
    uint32_t dstOff = (uint32_t)(aRow * WPAD + half * 8) * 4u;
    uint32_t sAb = smem_u32(&sA[0][0]);
    uint32_t sBb = smem_u32(&sB[0][0]);
    const uint32_t BUFB = 128u * WPAD * 4u;

    float acc[4][4][4];
    #pragma unroll
    for (int i = 0; i < 4; i++)
        #pragma unroll
        for (int j = 0; j < 4; j++)
            #pragma unroll
            for (int v = 0; v < 4; v++) acc[i][j][v] = 0.0f;

    int nch = K >> 5;

    // ---- prologue: tile 0 -> buffer 0 ----
    if (ABF) {
        cpasync16(sAb + dstOff, Agb);
        cpasync16(sAb + dstOff + 16, Agb + 8);
    } else {
        float4 a0 = *(const float4*)(Agf);
        float4 a1 = *(const float4*)(Agf + 4);
        float4 a2 = *(const float4*)(Agf + 8);
        float4 a3 = *(const float4*)(Agf + 12);
        uint32_t* dA = &sA[0][aRow * WPAD + half * 8];
        __nv_bfloat162 h;
        h = __floats2bfloat162_rn(a0.x, a0.y); dA[0] = *(uint32_t*)&h;
        h = __floats2bfloat162_rn(a0.z, a0.w); dA[1] = *(uint32_t*)&h;
        h = __floats2bfloat162_rn(a1.x, a1.y); dA[2] = *(uint32_t*)&h;
        h = __floats2bfloat162_rn(a1.z, a1.w); dA[3] = *(uint32_t*)&h;
        h = __floats2bfloat162_rn(a2.x, a2.y); dA[4] = *(uint32_t*)&h;
        h = __floats2bfloat162_rn(a2.z, a2.w); dA[5] = *(uint32_t*)&h;
        h = __floats2bfloat162_rn(a3.x, a3.y); dA[6] = *(uint32_t*)&h;
        h = __floats2bfloat162_rn(a3.z, a3.w); dA[7] = *(uint32_t*)&h;
    }
    cpasync16(sBb + dstOff, Bg);
    cpasync16(sBb + dstOff + 16, Bg + 8);
    CP_COMMIT();
    CP_WAIT0();
    __syncthreads();

    for (int i = 0; i < nch; i++) {
        int b = i & 1;
        bool more = (i + 1) < nch;
        float4 na0, na1, na2, na3;
        if (more) {
            uint32_t off = (uint32_t)(b ^ 1) * BUFB + dstOff;
            if (ABF) {
                const __nv_bfloat16* ag = Agb + (size_t)(i + 1) * 32;
                cpasync16(sAb + off, ag);
                cpasync16(sAb + off + 16, ag + 8);
            } else {
                const float* ag = Agf + (size_t)(i + 1) * 32;
                na0 = *(const float4*)(ag);
                na1 = *(const float4*)(ag + 4);
                na2 = *(const float4*)(ag + 8);
                na3 = *(const float4*)(ag + 12);
            }
            const __nv_bfloat16* bg = Bg + (size_t)(i + 1) * 32;
            cpasync16(sBb + off, bg);
            cpasync16(sBb + off + 16, bg + 8);
            CP_COMMIT();
        }

        const uint32_t* Ab = sA[b];
        const uint32_t* Bb = sB[b];
        #pragma unroll
        for (int ksp = 0; ksp < 2; ksp++) {
            uint32_t af[4][4], bf[4][2];
            #pragma unroll
            for (int mt = 0; mt < 4; mt++) {
                int r = warp_m * 64 + mt * 16 + qr;
                af[mt][0] = Ab[(r)     * WPAD + ksp * 8 + qc];
                af[mt][1] = Ab[(r + 8) * WPAD + ksp * 8 + qc];
                af[mt][2] = Ab[(r)     * WPAD + ksp * 8 + qc + 4];
                af[mt][3] = Ab[(r + 8) * WPAD + ksp * 8 + qc + 4];
            }
            #pragma unroll
            for (int nt = 0; nt < 4; nt++) {
                int cn = warp_n * 32 + nt * 8 + qr;
                bf[nt][0] = Bb[cn * WPAD + ksp * 8 + qc];
                bf[nt][1] = Bb[cn * WPAD + ksp * 8 + qc + 4];
            }
            #pragma unroll
            for (int mt = 0; mt < 4; mt++)
                #pragma unroll
                for (int nt = 0; nt < 4; nt++) {
                    asm volatile(
                        "mma.sync.aligned.m16n8k16.row.col.f32.bf16.bf16.f32 "
                        "{%0,%1,%2,%3}, {%4,%5,%6,%7}, {%8,%9}, {%0,%1,%2,%3};"
                        : "+f"(acc[mt][nt][0]), "+f"(acc[mt][nt][1]),
                          "+f"(acc[mt][nt][2]), "+f"(acc[mt][nt][3])
                        : "r"(af[mt][0]), "r"(af[mt][1]), "r"(af[mt][2]), "r"(af[mt][3]),
                          "r"(bf[nt][0]), "r"(bf[nt][1]));
                }
        }

        if (more) {
            if (!ABF) {
                uint32_t* dA = &sA[b ^ 1][aRow * WPAD + half * 8];
                __nv_bfloat162 h;
                h = __floats2bfloat162_rn(na0.x, na0.y); dA[0] = *(uint32_t*)&h;
                h = __floats2bfloat162_rn(na0.z, na0.w); dA[1] = *(uint32_t*)&h;
                h = __floats2bfloat162_rn(na1.x, na1.y); dA[2] = *(uint32_t*)&h;
                h = __floats2bfloat162_rn(na1.z, na1.w); dA[3] = *(uint32_t*)&h;
                h = __floats2bfloat162_rn(na2.x, na2.y); dA[4] = *(uint32_t*)&h;
                h = __floats2bfloat162_rn(na2.z, na2.w); dA[5] = *(uint32_t*)&h;
                h = __floats2bfloat162_rn(na3.x, na3.y); dA[6] = *(uint32_t*)&h;
                h = __floats2bfloat162_rn(na3.z, na3.w); dA[7] = *(uint32_t*)&h;
            }
            CP_WAIT0();
        }
        __syncthreads();
    }

    // ---- epilogue ----
    #pragma unroll
    for (int nt = 0; nt < 4; nt++) {
        int col = n0 + warp_n * 32 + nt * 8 + qc * 2;
        float bx = bias[col], by = bias[col + 1];
        float cs0 = 0.f, cs1 = 0.f;
        #pragma unroll
        for (int mt = 0; mt < 4; mt++) {
            int row = m0 + warp_m * 64 + mt * 16 + qr;
            float v0 = acc[mt][nt][0] + bx;
            float v1 = acc[mt][nt][1] + by;
            float v2 = acc[mt][nt][2] + bx;
            float v3 = acc[mt][nt][3] + by;
            if (DOMEAN) { cs0 += v0 + v2; cs1 += v1 + v3; }
            if (EPI == 1) {
                __nv_bfloat162 ha = __floats2bfloat162_rn(gelu_exact(v0), gelu_exact(v1));
                __nv_bfloat162 hb = __floats2bfloat162_rn(gelu_exact(v2), gelu_exact(v3));
                __nv_bfloat16* cb = (__nv_bfloat16*)Cout;
                *(__nv_bfloat162*)(cb + (size_t)row * N + col)       = ha;
                *(__nv_bfloat162*)(cb + (size_t)(row + 8) * N + col) = hb;
            } else {
                if (EPI == 2) {
                    float2 ra = *(const float2*)(R + (size_t)row * N + col);
                    float2 rb = *(const float2*)(R + (size_t)(row + 8) * N + col);
                    v0 += ra.x; v1 += ra.y; v2 += rb.x; v3 += rb.y;
                }
                float* cf = (float*)Cout;
                float2 oa; oa.x = v0; oa.y = v1;
                float2 ob; ob.x = v2; ob.y = v3;
                *(float2*)(cf + (size_t)row * N + col)       = oa;
                *(float2*)(cf + (size_t)(row + 8) * N + col) = ob;
            }
        }
        if (DOMEAN && n0 < 512) {
            #pragma unroll
            for (int o = 4; o <= 16; o <<= 1) {
                cs0 += __shfl_xor_sync(0xffffffffu, cs0, o);
                cs1 += __shfl_xor_sync(0xffffffffu, cs1, o);
            }
            if (qr == 0) {
                int win = blockIdx.y * 2 + warp_m;
                float mv0 = cs0 * (1.0f / 64.0f);
                float mv1 = cs1 * (1.0f / 64.0f);
                if (col < 256) {
                    qw[win * CDIM + col]     = mv0;
                    qw[win * CDIM + col + 1] = mv1;
                } else {
                    kw[win * CDIM + col - 256] = mv0;
                    kw[win * CDIM + col - 255] = mv1;
                }
            }
        }
    }
}

// ---------------- router: warp-per-logit, coalesced + shfl reduce ----------------
__global__ void router_kernel(const float* __restrict__ qw, const float* __restrict__ kw,
                              int* __restrict__ topk) {
    int np = blockIdx.x;
    int n = np / NWIN;
    int tid = threadIdx.x;
    int warp = tid >> 5, lane = tid & 31;
    __shared__ float qs[CDIM];
    __shared__ float lg[64];
    qs[tid] = qw[np * CDIM + tid] * WSCALE;
    __syncthreads();
    for (int q = warp; q < NWIN; q += 8) {
        const float* kr = kw + (size_t)(n * NWIN + q) * CDIM;
        float s = 0.f;
        #pragma unroll
        for (int h = 0; h < 2; h++) {
            float4 kv = ((const float4*)kr)[h * 32 + lane];
            float4 qv = ((const float4*)qs)[h * 32 + lane];
            s += kv.x * qv.x + kv.y * qv.y + kv.z * qv.z + kv.w * qv.w;
        }
        #pragma unroll
        for (int o = 16; o; o >>= 1) s += __shfl_xor_sync(0xffffffffu, s, o);
        if (lane == 0) lg[q] = s;
    }
    __syncthreads();
    if (tid == 0) {
        bool used[NWIN];
        #pragma unroll
        for (int i = 0; i < NWIN; i++) used[i] = false;
        for (int r = 0; r < 4; r++) {
            float best = -1e30f; int bi = 0;
            for (int q = 0; q < NWIN; q++)
                if (!used[q] && lg[q] > best) { best = lg[q]; bi = q; }
            used[bi] = true;
            topk[np * 4 + r] = bi;
        }
    }
}

// ---------------- tensor-core gathered attention (TF32 mma), online softmax ----------
#define KS_STRIDE 36
#define VS_STRIDE 40
#define PS_STRIDE 68
__global__ __launch_bounds__(64)
void attn_kernel(const float* __restrict__ QKV, const int* __restrict__ topk,
                 float* __restrict__ O) {
    __shared__ float ks[64][KS_STRIDE];
    __shared__ float vs[64][VS_STRIDE];
    __shared__ float ps[64][PS_STRIDE];

    int np = blockIdx.x, mh = blockIdx.y;
    int n = np / NWIN, p = np % NWIN;
    int tid = threadIdx.x, warp = tid >> 5, lane = tid & 31;
    int qr = lane >> 2, qc = lane & 3;

    const float* qbase = QKV + (size_t)np * 64 * QKC + mh * 32;
    for (int i = tid; i < 512; i += 64) {
        int r = i >> 3, c = (i & 7) * 4;
        float4 v = *(const float4*)(qbase + (size_t)r * QKC + c);
        ps[r][c + 0] = tf32f(v.x * WSCALE);
        ps[r][c + 1] = tf32f(v.y * WSCALE);
        ps[r][c + 2] = tf32f(v.z * WSCALE);
        ps[r][c + 3] = tf32f(v.w * WSCALE);
    }
    __syncthreads();

    uint32_t qf[2][4][4];
    #pragma unroll
    for (int mt = 0; mt < 2; mt++) {
        int r = warp * 32 + mt * 16 + qr;
        #pragma unroll
        for (int kk = 0; kk < 4; kk++) {
            qf[mt][kk][0] = __float_as_uint(ps[r][kk * 8 + qc]);
            qf[mt][kk][1] = __float_as_uint(ps[r + 8][kk * 8 + qc]);
            qf[mt][kk][2] = __float_as_uint(ps[r][kk * 8 + qc + 4]);
            qf[mt][kk][3] = __float_as_uint(ps[r + 8][kk * 8 + qc + 4]);
        }
    }
    __syncthreads();

    float mrun[4] = {-1e30f, -1e30f, -1e30f, -1e30f};
    float lrun[4] = {0.f, 0.f, 0.f, 0.f};
    float oacc[2][4][4];
    #pragma unroll
    for (int mt = 0; mt < 2; mt++)
        #pragma unroll
        for (int nt = 0; nt < 4; nt++)
            #pragma unroll
            for (int v = 0; v < 4; v++) oacc[mt][nt][v] = 0.f;

    for (int t4 = 0; t4 < 4; t4++) {
        int rwin = topk[np * 4 + t4];
        const float* kb = QKV + (size_t)(n * NWIN + rwin) * 64 * QKC + 256 + mh * 32;
        for (int i = tid; i < 512; i += 64) {
            int r = i >> 3, c = (i & 7) * 4;
            float4 kv = *(const float4*)(kb + (size_t)r * QKC + c);
            ks[r][c + 0] = tf32f(kv.x); ks[r][c + 1] = tf32f(kv.y);
            ks[r][c + 2] = tf32f(kv.z); ks[r][c + 3] = tf32f(kv.w);
            float4 vv = *(const float4*)(kb + (size_t)r * QKC + 256 + c);
            vs[r][c + 0] = tf32f(vv.x); vs[r][c + 1] = tf32f(vv.y);
            vs[r][c + 2] = tf32f(vv.z); vs[r][c + 3] = tf32f(vv.w);
        }
        __syncthreads();

        float sacc[2][8][4];
        #pragma unroll
        for (int mt = 0; mt < 2; mt++)
            #pragma unroll
            for (int nt = 0; nt < 8; nt++)
                #pragma unroll
                for (int v = 0; v < 4; v++) sacc[mt][nt][v] = 0.f;

        #pragma unroll
        for (int kk = 0; kk < 4; kk++) {
            uint32_t bf[8][2];
            #pragma unroll
            for (int nt = 0; nt < 8; nt++) {
                bf[nt][0] = __float_as_uint(ks[nt * 8 + qr][kk * 8 + qc]);
                bf[nt][1] = __float_as_uint(ks[nt * 8 + qr][kk * 8 + qc + 4]);
            }
            #pragma unroll
            for (int mt = 0; mt < 2; mt++)
                #pragma unroll
                for (int nt = 0; nt < 8; nt++) {
                    asm volatile(
                        "mma.sync.aligned.m16n8k8.row.col.f32.tf32.tf32.f32 "
                        "{%0,%1,%2,%3}, {%4,%5,%6,%7}, {%8,%9}, {%0,%1,%2,%3};"
                        : "+f"(sacc[mt][nt][0]), "+f"(sacc[mt][nt][1]),
                          "+f"(sacc[mt][nt][2]), "+f"(sacc[mt][nt][3])
                        : "r"(qf[mt][kk][0]), "r"(qf[mt][kk][1]),
                          "r"(qf[mt][kk][2]), "r"(qf[mt][kk][3]),
                          "r"(bf[nt][0]), "r"(bf[nt][1]));
                }
        }

        float rmax[4] = {-1e30f, -1e30f, -1e30f, -1e30f};
        #pragma unroll
        for (int mt = 0; mt < 2; mt++)
            #pragma unroll
            for (int nt = 0; nt < 8; nt++) {
                rmax[mt * 2 + 0] = fmaxf(rmax[mt * 2 + 0], fmaxf(sacc[mt][nt][0], sacc[mt][nt][1]));
                rmax[mt * 2 + 1] = fmaxf(rmax[mt * 2 + 1], fmaxf(sacc[mt][nt][2], sacc[mt][nt][3]));
            }
        #pragma unroll
        for (int g = 0; g < 4; g++) {
            rmax[g] = fmaxf(rmax[g], __shfl_xor_sync(0xffffffffu, rmax[g], 1));
            rmax[g] = fmaxf(rmax[g], __shfl_xor_sync(0xffffffffu, rmax[g], 2));
        }
        float corr[4], mnew[4];
        #pragma unroll
        for (int g = 0; g < 4; g++) {
            mnew[g] = fmaxf(mrun[g], rmax[g]);
            corr[g] = __expf(mrun[g] - mnew[g]);
            lrun[g] *= corr[g];
            mrun[g] = mnew[g];
        }
        #pragma unroll
        for (int mt = 0; mt < 2; mt++)
            #pragma unroll
            for (int nt = 0; nt < 4; nt++) {
                oacc[mt][nt][0] *= corr[mt * 2 + 0];
                oacc[mt][nt][1] *= corr[mt * 2 + 0];
                oacc[mt][nt][2] *= corr[mt * 2 + 1];
                oacc[mt][nt][3] *= corr[mt * 2 + 1];
            }
        float psum[4] = {0.f, 0.f, 0.f, 0.f};
        #pragma unroll
        for (int mt = 0; mt < 2; mt++) {
            int r0 = warp * 32 + mt * 16 + qr;
            #pragma unroll
            for (int nt = 0; nt < 8; nt++) {
                float p0 = __expf(sacc[mt][nt][0] - mnew[mt * 2 + 0]);
                float p1 = __expf(sacc[mt][nt][1] - mnew[mt * 2 + 0]);
                float p2 = __expf(sacc[mt][nt][2] - mnew[mt * 2 + 1]);
                float p3 = __expf(sacc[mt][nt][3] - mnew[mt * 2 + 1]);
                psum[mt * 2 + 0] += p0 + p1;
                psum[mt * 2 + 1] += p2 + p3;
                float2 w0; w0.x = tf32f(p0); w0.y = tf32f(p1);
                float2 w1; w1.x = tf32f(p2); w1.y = tf32f(p3);
                *(float2*)&ps[r0][nt * 8 + qc * 2]     = w0;
                *(float2*)&ps[r0 + 8][nt * 8 + qc * 2] = w1;
            }
        }
        #pragma unroll
        for (int g = 0; g < 4; g++) {
            psum[g] += __shfl_xor_sync(0xffffffffu, psum[g], 1);
            psum[g] += __shfl_xor_sync(0xffffffffu, psum[g], 2);
            lrun[g] += psum[g];
        }
        __syncwarp();

        #pragma unroll
        for (int kt = 0; kt < 8; kt++) {
            uint32_t af[2][4], bf[4][2];
            #pragma unroll
            for (int mt = 0; mt < 2; mt++) {
                int r = warp * 32 + mt * 16 + qr;
                af[mt][0] = __float_as_uint(ps[r][kt * 8 + qc]);
                af[mt][1] = __float_as_uint(ps[r + 8][kt * 8 + qc]);
                af[mt][2] = __float_as_uint(ps[r][kt * 8 + qc + 4]);
                af[mt][3] = __float_as_uint(ps[r + 8][kt * 8 + qc + 4]);
            }
            #pragma unroll
            for (int nt = 0; nt < 4; nt++) {
                bf[nt][0] = __float_as_uint(vs[kt * 8 + qc][nt * 8 + qr]);
                bf[nt][1] = __float_as_uint(vs[kt * 8 + qc + 4][nt * 8 + qr]);
            }
            #pragma unroll
            for (int mt = 0; mt < 2; mt++)
                #pragma unroll
                for (int nt = 0; nt < 4; nt++) {
                    asm volatile(
                        "mma.sync.aligned.m16n8k8.row.col.f32.tf32.tf32.f32 "
                        "{%0,%1,%2,%3}, {%4,%5,%6,%7}, {%8,%9}, {%0,%1,%2,%3};"
                        : "+f"(oacc[mt][nt][0]), "+f"(oacc[mt][nt][1]),
                          "+f"(oacc[mt][nt][2]), "+f"(oacc[mt][nt][3])
                        : "r"(af[mt][0]), "r"(af[mt][1]), "r"(af[mt][2]), "r"(af[mt][3]),
                          "r"(bf[nt][0]), "r"(bf[nt][1]));
                }
        }
        __syncthreads();
    }

    float linv[4];
    #pragma unroll
    for (int g = 0; g < 4; g++) linv[g] = 1.0f / lrun[g];

    int jj = p / 7, ii = p % 7;
    #pragma unroll
    for (int mt = 0; mt < 2; mt++) {
        #pragma unroll
        for (int half = 0; half < 2; half++) {
            int q = warp * 32 + mt * 16 + qr + half * 8;
            int y = jj * 8 + (q >> 3), x = ii * 8 + (q & 7);
            float* orow = O + ((size_t)(n * HWDIM + y) * HWDIM + x) * CDIM + mh * 32;
            float li = linv[mt * 2 + half];
            #pragma unroll
            for (int nt = 0; nt < 4; nt++) {
                float2 v;
                v.x = oacc[mt][nt][half * 2 + 0] * li;
                v.y = oacc[mt][nt][half * 2 + 1] * li;
                *(float2*)(orow + nt * 8 + qc * 2) = v;
            }
        }
    }
}

// ---------------- 5x5 depthwise lepe, smem-tiled, accumulates into O ----------------
__global__ __launch_bounds__(256)
void lepe_kernel(const float* __restrict__ QKV, const float* __restrict__ W,
                 const float* __restrict__ B, float* __restrict__ O) {
    __shared__ float sv[144][64];
    __shared__ float sw[25][64];
    int np = blockIdx.x, cg = blockIdx.y;
    int n = np / NWIN, p = np % NWIN;
    int jj = p / 7, ii = p % 7;
    int tid = threadIdx.x;

    for (int i = tid; i < 1600; i += 256)
        sw[i / 64][i % 64] = W[(i / 64) * CDIM + cg * 64 + (i % 64)];

    for (int i = tid; i < 2304; i += 256) {
        int pos = i >> 4, c4 = i & 15;
        int yy = jj * 8 + (pos / 12) - 2;
        int xx = ii * 8 + (pos % 12) - 2;
        float4 v = make_float4(0.f, 0.f, 0.f, 0.f);
        if (yy >= 0 && yy < HWDIM && xx >= 0 && xx < HWDIM) {
            int pp = (yy >> 3) * 7 + (xx >> 3);
            int qi = (yy & 7) * 8 + (xx & 7);
            const float* src = QKV + ((size_t)(n * NWIN + pp) * 64 + qi) * QKC + 512 + cg * 64;
            v = *(const float4*)(src + c4 * 4);
        }
        *(float4*)&sv[pos][c4 * 4] = v;
    }
    __syncthreads();

    int c = tid & 63, pp0 = tid >> 6;
    float wr[25];
    #pragma unroll
    for (int t5 = 0; t5 < 25; t5++) wr[t5] = sw[t5][c];
    float bias = B[cg * 64 + c];

    #pragma unroll
    for (int hi = 0; hi < 2; hi++) {
        int hh = pp0 + hi * 4;
        #pragma unroll
        for (int ww = 0; ww < 8; ww++) {
            float acc = bias;
            #pragma unroll
            for (int dy = 0; dy < 5; dy++)
                #pragma unroll
                for (int dx = 0; dx < 5; dx++)
                    acc += sv[(hh + dy) * 12 + (ww + dx)][c] * wr[dy * 5 + dx];
            int y = jj * 8 + hh, x = ii * 8 + ww;
            int t = (n * HWDIM + y) * HWDIM + x;
            O[(size_t)t * CDIM + cg * 64 + c] += acc;
        }
    }
}

// ---------------- host launch ----------------
extern "C" void kernel_launch(void* const* d_in, const int* in_sizes, int n_in,
                              void* d_out, int out_size) {
    const float* x      = (const float*)d_in[0];
    const float* ln1_g  = (const float*)d_in[1];
    const float* ln1_b  = (const float*)d_in[2];
    const float* qkv_w  = (const float*)d_in[3];
    const float* qkv_b  = (const float*)d_in[4];
    const float* lepe_w = (const float*)d_in[5];
    const float* lepe_b = (const float*)d_in[6];
    const float* wo_w   = (const float*)d_in[7];
    const float* wo_b   = (const float*)d_in[8];
    const float* ln2_g  = (const float*)d_in[9];
    const float* ln2_b  = (const float*)d_in[10];
    const float* mlp_w1 = (const float*)d_in[11];
    const float* mlp_b1 = (const float*)d_in[12];
    const float* mlp_w2 = (const float*)d_in[13];
    const float* mlp_b2 = (const float*)d_in[14];
    float* out = (float*)d_out;

    float *tmp, *qkv, *x1, *hid, *qw, *kw;
    int* tk;
    __nv_bfloat16* wbf;
    cudaGetSymbolAddress((void**)&tmp, g_tmp256);
    cudaGetSymbolAddress((void**)&qkv, g_qkv);
    cudaGetSymbolAddress((void**)&x1,  g_x1);
    cudaGetSymbolAddress((void**)&hid, g_hid);
    cudaGetSymbolAddress((void**)&qw,  g_qwin);
    cudaGetSymbolAddress((void**)&kw,  g_kwin);
    cudaGetSymbolAddress((void**)&tk,  g_topk);
    cudaGetSymbolAddress((void**)&wbf, g_wbf);
    __nv_bfloat16* tmpb = (__nv_bfloat16*)tmp;
    __nv_bfloat16* hidb = (__nv_bfloat16*)hid;

    // 0. transpose + bf16-convert weights
    wtrans_kernel<<<dim3(CDIM / 32, QKC / 32), 256>>>(qkv_w,  wbf + WT_QKV, CDIM, QKC);
    wtrans_kernel<<<dim3(CDIM / 32, CDIM / 32), 256>>>(wo_w,  wbf + WT_WO,  CDIM, CDIM);
    wtrans_kernel<<<dim3(CDIM / 32, HIDC / 32), 256>>>(mlp_w1, wbf + WT_W1, CDIM, HIDC);
    wtrans_kernel<<<dim3(HIDC / 32, CDIM / 32), 256>>>(mlp_w2, wbf + WT_W2, HIDC, CDIM);

    // 1. LN1 with window permute -> bf16
    ln_kernel<true><<<TOK / 8, 256>>>(x, ln1_g, ln1_b, tmpb);
    // 2. qkv GEMM (bf16 A, fused window means)
    tgemm_kernel<0, 1, 1><<<dim3(QKC / 128, TOK / 128), 256>>>(
        tmpb, wbf + WT_QKV, qkv_b, nullptr, qkv, qw, kw, TOK, QKC, CDIM);
    // 3. router + top-4
    router_kernel<<<NPALL, 256>>>(qw, kw, tk);
    // 4. gathered attention -> fp32 tmp (image order)
    attn_kernel<<<dim3(NPALL, 8), 64>>>(qkv, tk, tmp);
    // 5. lepe depthwise conv accumulates into tmp
    lepe_kernel<<<dim3(NPALL, 4), 256>>>(qkv, lepe_w, lepe_b, tmp);
    // 6. wo GEMM (fp32 A) + residual -> x1
    tgemm_kernel<2, 0, 0><<<dim3(CDIM / 128, TOK / 128), 256>>>(
        tmp, wbf + WT_WO, wo_b, x, x1, nullptr, nullptr, TOK, CDIM, CDIM);
    // 7. LN2 -> bf16
    ln_kernel<false><<<TOK / 8, 256>>>(x1, ln2_g, ln2_b, tmpb);
    // 8. MLP1 + GELU -> bf16 hid
    tgemm_kernel<1, 1, 0><<<dim3(HIDC / 128, TOK / 128), 256>>>(
        tmpb, wbf + WT_W1, mlp_b1, nullptr, hidb, nullptr, nullptr, TOK, HIDC, CDIM);
    // 9. MLP2 (bf16 A) + residual -> out
    tgemm_kernel<2, 1, 0><<<dim3(CDIM / 128, TOK / 128), 256>>>(
        hidb, wbf + WT_W2, mlp_b2, x1, out, nullptr, nullptr, TOK, CDIM, HIDC);
}

// round 12
// speedup vs baseline: 4.1353x; 1.0080x over previous
#include <cuda_runtime.h>
#include <cuda_bf16.h>
#include <math.h>
#include <stdint.h>

// ---------------- problem constants ----------------
#define TOK    25088      // 8*56*56
#define NBATCH 8
#define HWDIM  56
#define CDIM   256
#define QKC    768        // qkv width
#define HIDC   1024
#define NWIN   49         // 7*7 windows per image
#define NPALL  392        // 8*49
#define WSCALE 0.0625f    // 256^-0.5

// ---------------- scratch (device globals; no allocs allowed) ----------------
__device__ __align__(256) float g_tmp256[TOK * CDIM];   // ln1(bf16) / lepe(f32) / ln2(bf16)
__device__ __align__(256) float g_qkv[TOK * QKC];
__device__ __align__(256) float g_x1[TOK * CDIM];
__device__ __align__(256) float g_hid[(size_t)TOK * HIDC / 2];  // bf16 storage (attn-out, then mlp hid)
__device__ float g_qwin[NPALL * CDIM];
__device__ float g_kwin[NPALL * CDIM];
__device__ int   g_topk[NPALL * 4];
__device__ __align__(256) __nv_bfloat16 g_wbf[786432];  // transposed bf16 weights

#define WT_QKV 0
#define WT_WO  196608
#define WT_W1  262144
#define WT_W2  524288

__device__ __forceinline__ uint32_t f2tf32(float x) {
    uint32_t u;
    asm("cvt.rna.tf32.f32 %0, %1;" : "=r"(u) : "f"(x));
    return u;
}
__device__ __forceinline__ float tf32f(float x) { return __uint_as_float(f2tf32(x)); }

__device__ __forceinline__ uint32_t smem_u32(const void* p) {
    uint32_t a;
    asm("{ .reg .u64 t; cvta.to.shared.u64 t, %1; cvt.u32.u64 %0, t; }" : "=r"(a) : "l"(p));
    return a;
}
__device__ __forceinline__ void cpasync16(uint32_t s, const void* g) {
    asm volatile("cp.async.cg.shared.global [%0], [%1], 16;" :: "r"(s), "l"(g) : "memory");
}
#define CP_COMMIT() asm volatile("cp.async.commit_group;" ::: "memory")
#define CP_WAIT0()  asm volatile("cp.async.wait_group 0;" ::: "memory")

// ---------------- merged weight transpose + bf16 convert (all 4 weights) --------------
// tiles: qkv 8x24=192, wo 8x8=64, w1 8x32=256, w2 32x8=256  -> 768 blocks total
__global__ void wtrans_all_kernel(const float* __restrict__ qkv_w, const float* __restrict__ wo_w,
                                  const float* __restrict__ w1, const float* __restrict__ w2,
                                  __nv_bfloat16* __restrict__ wbf) {
    __shared__ float tile[32][33];
    int b = blockIdx.x;
    const float* W; __nv_bfloat16* WT; int K, N, t;
    if (b < 192)      { W = qkv_w; WT = wbf + WT_QKV; K = CDIM; N = QKC;  t = b; }
    else if (b < 256) { W = wo_w;  WT = wbf + WT_WO;  K = CDIM; N = CDIM; t = b - 192; }
    else if (b < 512) { W = w1;    WT = wbf + WT_W1;  K = CDIM; N = HIDC; t = b - 256; }
    else              { W = w2;    WT = wbf + WT_W2;  K = HIDC; N = CDIM; t = b - 512; }
    int ktiles = K >> 5;
    int k0 = (t % ktiles) * 32, n0 = (t / ktiles) * 32;
    int tx = threadIdx.x & 31, ty = threadIdx.x >> 5;   // 32 x 8
    #pragma unroll
    for (int i = ty; i < 32; i += 8)
        tile[i][tx] = W[(size_t)(k0 + i) * N + n0 + tx];
    __syncthreads();
    #pragma unroll
    for (int i = ty; i < 32; i += 8)
        WT[(size_t)(n0 + i) * K + k0 + tx] = __float2bfloat16(tile[tx][i]);
}

// ---------------- LayerNorm (warp per token) -> bf16 out, optional window permute ----
template<bool PERM>
__global__ void ln_kernel(const float* __restrict__ X, const float* __restrict__ gam,
                          const float* __restrict__ bet, __nv_bfloat16* __restrict__ Y) {
    int warp = threadIdx.x >> 5, lane = threadIdx.x & 31;
    int t = blockIdx.x * 8 + warp;
    const float* row = X + (size_t)t * CDIM;
    float4 v0 = *(const float4*)(row + lane * 8);
    float4 v1 = *(const float4*)(row + lane * 8 + 4);
    float s  = v0.x + v0.y + v0.z + v0.w + v1.x + v1.y + v1.z + v1.w;
    float sq = v0.x*v0.x + v0.y*v0.y + v0.z*v0.z + v0.w*v0.w
             + v1.x*v1.x + v1.y*v1.y + v1.z*v1.z + v1.w*v1.w;
    #pragma unroll
    for (int o = 16; o; o >>= 1) {
        s  += __shfl_xor_sync(0xffffffffu, s, o);
        sq += __shfl_xor_sync(0xffffffffu, sq, o);
    }
    float mu  = s * (1.0f / 256.0f);
    float var = sq * (1.0f / 256.0f) - mu * mu;
    float inv = rsqrtf(var + 1e-6f);

    int orow;
    if (PERM) {
        int n = t / 3136, rem = t % 3136;
        int y = rem / 56, x = rem % 56;
        int p  = (y >> 3) * 7 + (x >> 3);
        int qi = (y & 7) * 8 + (x & 7);
        orow = (n * NWIN + p) * 64 + qi;
    } else {
        orow = t;
    }
    float4 g0 = *(const float4*)(gam + lane * 8);
    float4 g1 = *(const float4*)(gam + lane * 8 + 4);
    float4 b0 = *(const float4*)(bet + lane * 8);
    float4 b1 = *(const float4*)(bet + lane * 8 + 4);
    __nv_bfloat162 o0 = __floats2bfloat162_rn((v0.x - mu) * inv * g0.x + b0.x,
                                              (v0.y - mu) * inv * g0.y + b0.y);
    __nv_bfloat162 o1 = __floats2bfloat162_rn((v0.z - mu) * inv * g0.z + b0.z,
                                              (v0.w - mu) * inv * g0.w + b0.w);
    __nv_bfloat162 o2 = __floats2bfloat162_rn((v1.x - mu) * inv * g1.x + b1.x,
                                              (v1.y - mu) * inv * g1.y + b1.y);
    __nv_bfloat162 o3 = __floats2bfloat162_rn((v1.z - mu) * inv * g1.z + b1.z,
                                              (v1.w - mu) * inv * g1.w + b1.w);
    uint4 pk;
    pk.x = *(uint32_t*)&o0; pk.y = *(uint32_t*)&o1;
    pk.z = *(uint32_t*)&o2; pk.w = *(uint32_t*)&o3;
    *(uint4*)(Y + (size_t)orow * CDIM + lane * 8) = pk;
}

// ---------------- BF16 tensor-core GEMM 128x128x32, 256 threads, cp.async staged ------
// EPI: 0 bias, 1 bias+GELU (bf16 out), 2 bias+residual (fp32 out)
// ABF: A operand bf16 (pure cp.async) vs fp32 (ld+cvt+STS)
// DOMEAN: fused per-window column means into qw/kw (qkv GEMM only)
__device__ __forceinline__ float gelu_exact(float x) {
    return 0.5f * x * (1.0f + erff(x * 0.70710678118654752440f));
}

#define WPAD 20   // row stride in 32-bit words (bf16 pairs); 16 data + 4 pad

template<int EPI, int ABF, int DOMEAN>
__global__ __launch_bounds__(256)
void tgemm_kernel(const void* __restrict__ Ain, const __nv_bfloat16* __restrict__ WT,
                  const float* __restrict__ bias, const float* __restrict__ R,
                  void* __restrict__ Cout, float* __restrict__ qw, float* __restrict__ kw,
                  int M, int N, int K) {
    __shared__ uint32_t sA[2][128 * WPAD];
    __shared__ uint32_t sB[2][128 * WPAD];

    int tid = threadIdx.x;
    int warp = tid >> 5, lane = tid & 31;
    int qr = lane >> 2, qc = lane & 3;
    int warp_m = warp >> 2, warp_n = warp & 3;   // 2 x 4
    int m0 = blockIdx.y * 128, n0 = blockIdx.x * 128;

    int aRow = tid >> 1, half = tid & 1;
    const __nv_bfloat16* Bg = WT + (size_t)(n0 + aRow) * K + half * 16;
    const __nv_bfloat16* Agb = (const __nv_bfloat16*)Ain + (size_t)(m0 + aRow) * K + half * 16;
    const float*         Agf = (const float*)Ain + (size_t)(m0 + aRow) * K + half * 16;
    uint32_t dstOff = (uint32_t)(aRow * WPAD + half * 8) * 4u;
    uint32_t sAb = smem_u32(&sA[0][0]);
    uint32_t sBb = smem_u32(&sB[0][0]);
    const uint32_t BUFB = 128u * WPAD * 4u;

    float acc[4][4][4];
    #pragma unroll
    for (int i = 0; i < 4; i++)
        #pragma unroll
        for (int j = 0; j < 4; j++)
            #pragma unroll
            for (int v = 0; v < 4; v++) acc[i][j][v] = 0.0f;

    int nch = K >> 5;

    // ---- prologue: tile 0 -> buffer 0 ----
    if (ABF) {
        cpasync16(sAb + dstOff, Agb);
        cpasync16(sAb + dstOff + 16, Agb + 8);
    } else {
        float4 a0 = *(const float4*)(Agf);
        float4 a1 = *(const float4*)(Agf + 4);
        float4 a2 = *(const float4*)(Agf + 8);
        float4 a3 = *(const float4*)(Agf + 12);
        uint32_t* dA = &sA[0][aRow * WPAD + half * 8];
        __nv_bfloat162 h;
        h = __floats2bfloat162_rn(a0.x, a0.y); dA[0] = *(uint32_t*)&h;
        h = __floats2bfloat162_rn(a0.z, a0.w); dA[1] = *(uint32_t*)&h;
        h = __floats2bfloat162_rn(a1.x, a1.y); dA[2] = *(uint32_t*)&h;
        h = __floats2bfloat162_rn(a1.z, a1.w); dA[3] = *(uint32_t*)&h;
        h = __floats2bfloat162_rn(a2.x, a2.y); dA[4] = *(uint32_t*)&h;
        h = __floats2bfloat162_rn(a2.z, a2.w); dA[5] = *(uint32_t*)&h;
        h = __floats2bfloat162_rn(a3.x, a3.y); dA[6] = *(uint32_t*)&h;
        h = __floats2bfloat162_rn(a3.z, a3.w); dA[7] = *(uint32_t*)&h;
    }
    cpasync16(sBb + dstOff, Bg);
    cpasync16(sBb + dstOff + 16, Bg + 8);
    CP_COMMIT();
    CP_WAIT0();
    __syncthreads();

    for (int i = 0; i < nch; i++) {
        int b = i & 1;
        bool more = (i + 1) < nch;
        float4 na0, na1, na2, na3;
        if (more) {
            uint32_t off = (uint32_t)(b ^ 1) * BUFB + dstOff;
            if (ABF) {
                const __nv_bfloat16* ag = Agb + (size_t)(i + 1) * 32;
                cpasync16(sAb + off, ag);
                cpasync16(sAb + off + 16, ag + 8);
            } else {
                const float* ag = Agf + (size_t)(i + 1) * 32;
                na0 = *(const float4*)(ag);
                na1 = *(const float4*)(ag + 4);
                na2 = *(const float4*)(ag + 8);
                na3 = *(const float4*)(ag + 12);
            }
            const __nv_bfloat16* bg = Bg + (size_t)(i + 1) * 32;
            cpasync16(sBb + off, bg);
            cpasync16(sBb + off + 16, bg + 8);
            CP_COMMIT();
        }

        const uint32_t* Ab = sA[b];
        const uint32_t* Bb = sB[b];
        #pragma unroll
        for (int ksp = 0; ksp < 2; ksp++) {
            uint32_t af[4][4], bf[4][2];
            #pragma unroll
            for (int mt = 0; mt < 4; mt++) {
                int r = warp_m * 64 + mt * 16 + qr;
                af[mt][0] = Ab[(r)     * WPAD + ksp * 8 + qc];
                af[mt][1] = Ab[(r + 8) * WPAD + ksp * 8 + qc];
                af[mt][2] = Ab[(r)     * WPAD + ksp * 8 + qc + 4];
                af[mt][3] = Ab[(r + 8) * WPAD + ksp * 8 + qc + 4];
            }
            #pragma unroll
            for (int nt = 0; nt < 4; nt++) {
                int cn = warp_n * 32 + nt * 8 + qr;
                bf[nt][0] = Bb[cn * WPAD + ksp * 8 + qc];
                bf[nt][1] = Bb[cn * WPAD + ksp * 8 + qc + 4];
            }
            #pragma unroll
            for (int mt = 0; mt < 4; mt++)
                #pragma unroll
                for (int nt = 0; nt < 4; nt++) {
                    asm volatile(
                        "mma.sync.aligned.m16n8k16.row.col.f32.bf16.bf16.f32 "
                        "{%0,%1,%2,%3}, {%4,%5,%6,%7}, {%8,%9}, {%0,%1,%2,%3};"
                        : "+f"(acc[mt][nt][0]), "+f"(acc[mt][nt][1]),
                          "+f"(acc[mt][nt][2]), "+f"(acc[mt][nt][3])
                        : "r"(af[mt][0]), "r"(af[mt][1]), "r"(af[mt][2]), "r"(af[mt][3]),
                          "r"(bf[nt][0]), "r"(bf[nt][1]));
                }
        }

        if (more) {
            if (!ABF) {
                uint32_t* dA = &sA[b ^ 1][aRow * WPAD + half * 8];
                __nv_bfloat162 h;
                h = __floats2bfloat162_rn(na0.x, na0.y); dA[0] = *(uint32_t*)&h;
                h = __floats2bfloat162_rn(na0.z, na0.w); dA[1] = *(uint32_t*)&h;
                h = __floats2bfloat162_rn(na1.x, na1.y); dA[2] = *(uint32_t*)&h;
                h = __floats2bfloat162_rn(na1.z, na1.w); dA[3] = *(uint32_t*)&h;
                h = __floats2bfloat162_rn(na2.x, na2.y); dA[4] = *(uint32_t*)&h;
                h = __floats2bfloat162_rn(na2.z, na2.w); dA[5] = *(uint32_t*)&h;
                h = __floats2bfloat162_rn(na3.x, na3.y); dA[6] = *(uint32_t*)&h;
                h = __floats2bfloat162_rn(na3.z, na3.w); dA[7] = *(uint32_t*)&h;
            }
            CP_WAIT0();
        }
        __syncthreads();
    }

    // ---- epilogue ----
    #pragma unroll
    for (int nt = 0; nt < 4; nt++) {
        int col = n0 + warp_n * 32 + nt * 8 + qc * 2;
        float bx = bias[col], by = bias[col + 1];
        float cs0 = 0.f, cs1 = 0.f;
        #pragma unroll
        for (int mt = 0; mt < 4; mt++) {
            int row = m0 + warp_m * 64 + mt * 16 + qr;
            float v0 = acc[mt][nt][0] + bx;
            float v1 = acc[mt][nt][1] + by;
            float v2 = acc[mt][nt][2] + bx;
            float v3 = acc[mt][nt][3] + by;
            if (DOMEAN) { cs0 += v0 + v2; cs1 += v1 + v3; }
            if (EPI == 1) {
                __nv_bfloat162 ha = __floats2bfloat162_rn(gelu_exact(v0), gelu_exact(v1));
                __nv_bfloat162 hb = __floats2bfloat162_rn(gelu_exact(v2), gelu_exact(v3));
                __nv_bfloat16* cb = (__nv_bfloat16*)Cout;
                *(__nv_bfloat162*)(cb + (size_t)row * N + col)       = ha;
                *(__nv_bfloat162*)(cb + (size_t)(row + 8) * N + col) = hb;
            } else {
                if (EPI == 2) {
                    float2 ra = *(const float2*)(R + (size_t)row * N + col);
                    float2 rb = *(const float2*)(R + (size_t)(row + 8) * N + col);
                    v0 += ra.x; v1 += ra.y; v2 += rb.x; v3 += rb.y;
                }
                float* cf = (float*)Cout;
                float2 oa; oa.x = v0; oa.y = v1;
                float2 ob; ob.x = v2; ob.y = v3;
                *(float2*)(cf + (size_t)row * N + col)       = oa;
                *(float2*)(cf + (size_t)(row + 8) * N + col) = ob;
            }
        }
        if (DOMEAN && n0 < 512) {
            #pragma unroll
            for (int o = 4; o <= 16; o <<= 1) {
                cs0 += __shfl_xor_sync(0xffffffffu, cs0, o);
                cs1 += __shfl_xor_sync(0xffffffffu, cs1, o);
            }
            if (qr == 0) {
                int win = blockIdx.y * 2 + warp_m;
                float mv0 = cs0 * (1.0f / 64.0f);
                float mv1 = cs1 * (1.0f / 64.0f);
                if (col < 256) {
                    qw[win * CDIM + col]     = mv0;
                    qw[win * CDIM + col + 1] = mv1;
                } else {
                    kw[win * CDIM + col - 256] = mv0;
                    kw[win * CDIM + col - 255] = mv1;
                }
            }
        }
    }
}

// ---------------- router: warp-per-logit, coalesced + shfl reduce ----------------
__global__ void router_kernel(const float* __restrict__ qw, const float* __restrict__ kw,
                              int* __restrict__ topk) {
    int np = blockIdx.x;
    int n = np / NWIN;
    int tid = threadIdx.x;
    int warp = tid >> 5, lane = tid & 31;
    __shared__ float qs[CDIM];
    __shared__ float lg[64];
    qs[tid] = qw[np * CDIM + tid] * WSCALE;
    __syncthreads();
    for (int q = warp; q < NWIN; q += 8) {
        const float* kr = kw + (size_t)(n * NWIN + q) * CDIM;
        float s = 0.f;
        #pragma unroll
        for (int h = 0; h < 2; h++) {
            float4 kv = ((const float4*)kr)[h * 32 + lane];
            float4 qv = ((const float4*)qs)[h * 32 + lane];
            s += kv.x * qv.x + kv.y * qv.y + kv.z * qv.z + kv.w * qv.w;
        }
        #pragma unroll
        for (int o = 16; o; o >>= 1) s += __shfl_xor_sync(0xffffffffu, s, o);
        if (lane == 0) lg[q] = s;
    }
    __syncthreads();
    if (tid == 0) {
        bool used[NWIN];
        #pragma unroll
        for (int i = 0; i < NWIN; i++) used[i] = false;
        for (int r = 0; r < 4; r++) {
            float best = -1e30f; int bi = 0;
            for (int q = 0; q < NWIN; q++)
                if (!used[q] && lg[q] > best) { best = lg[q]; bi = q; }
            used[bi] = true;
            topk[np * 4 + r] = bi;
        }
    }
}

// ---------------- 5x5 depthwise lepe, smem-tiled, WRITES O (first writer) ------------
__global__ __launch_bounds__(256)
void lepe_kernel(const float* __restrict__ QKV, const float* __restrict__ W,
                 const float* __restrict__ B, float* __restrict__ O) {
    __shared__ float sv[144][64];
    __shared__ float sw[25][64];
    int np = blockIdx.x, cg = blockIdx.y;
    int n = np / NWIN, p = np % NWIN;
    int jj = p / 7, ii = p % 7;
    int tid = threadIdx.x;

    for (int i = tid; i < 1600; i += 256)
        sw[i / 64][i % 64] = W[(i / 64) * CDIM + cg * 64 + (i % 64)];

    for (int i = tid; i < 2304; i += 256) {
        int pos = i >> 4, c4 = i & 15;
        int yy = jj * 8 + (pos / 12) - 2;
        int xx = ii * 8 + (pos % 12) - 2;
        float4 v = make_float4(0.f, 0.f, 0.f, 0.f);
        if (yy >= 0 && yy < HWDIM && xx >= 0 && xx < HWDIM) {
            int pp = (yy >> 3) * 7 + (xx >> 3);
            int qi = (yy & 7) * 8 + (xx & 7);
            const float* src = QKV + ((size_t)(n * NWIN + pp) * 64 + qi) * QKC + 512 + cg * 64;
            v = *(const float4*)(src + c4 * 4);
        }
        *(float4*)&sv[pos][c4 * 4] = v;
    }
    __syncthreads();

    int c = tid & 63, pp0 = tid >> 6;
    float wr[25];
    #pragma unroll
    for (int t5 = 0; t5 < 25; t5++) wr[t5] = sw[t5][c];
    float bias = B[cg * 64 + c];

    #pragma unroll
    for (int hi = 0; hi < 2; hi++) {
        int hh = pp0 + hi * 4;
        #pragma unroll
        for (int ww = 0; ww < 8; ww++) {
            float acc = bias;
            #pragma unroll
            for (int dy = 0; dy < 5; dy++)
                #pragma unroll
                for (int dx = 0; dx < 5; dx++)
                    acc += sv[(hh + dy) * 12 + (ww + dx)][c] * wr[dy * 5 + dx];
            int y = jj * 8 + hh, x = ii * 8 + ww;
            int t = (n * HWDIM + y) * HWDIM + x;
            O[(size_t)t * CDIM + cg * 64 + c] = acc;   // first writer
        }
    }
}

// ---------------- tensor-core gathered attention; adds lepe (from L) -> bf16 out -----
#define KS_STRIDE 36
#define VS_STRIDE 40
#define PS_STRIDE 68
__global__ __launch_bounds__(64)
void attn_kernel(const float* __restrict__ QKV, const int* __restrict__ topk,
                 const float* __restrict__ L, __nv_bfloat16* __restrict__ O) {
    __shared__ float ks[64][KS_STRIDE];
    __shared__ float vs[64][VS_STRIDE];
    __shared__ float ps[64][PS_STRIDE];   // Q stage (32 cols), then per-warp P (64 cols)

    int np = blockIdx.x, mh = blockIdx.y;
    int n = np / NWIN, p = np % NWIN;
    int tid = threadIdx.x, warp = tid >> 5, lane = tid & 31;
    int qr = lane >> 2, qc = lane & 3;

    const float* qbase = QKV + (size_t)np * 64 * QKC + mh * 32;
    for (int i = tid; i < 512; i += 64) {
        int r = i >> 3, c = (i & 7) * 4;
        float4 v = *(const float4*)(qbase + (size_t)r * QKC + c);
        ps[r][c + 0] = tf32f(v.x * WSCALE);
        ps[r][c + 1] = tf32f(v.y * WSCALE);
        ps[r][c + 2] = tf32f(v.z * WSCALE);
        ps[r][c + 3] = tf32f(v.w * WSCALE);
    }
    __syncthreads();

    uint32_t qf[2][4][4];
    #pragma unroll
    for (int mt = 0; mt < 2; mt++) {
        int r = warp * 32 + mt * 16 + qr;
        #pragma unroll
        for (int kk = 0; kk < 4; kk++) {
            qf[mt][kk][0] = __float_as_uint(ps[r][kk * 8 + qc]);
            qf[mt][kk][1] = __float_as_uint(ps[r + 8][kk * 8 + qc]);
            qf[mt][kk][2] = __float_as_uint(ps[r][kk * 8 + qc + 4]);
            qf[mt][kk][3] = __float_as_uint(ps[r + 8][kk * 8 + qc + 4]);
        }
    }
    __syncthreads();   // ps reused for P below

    float mrun[4] = {-1e30f, -1e30f, -1e30f, -1e30f};
    float lrun[4] = {0.f, 0.f, 0.f, 0.f};
    float oacc[2][4][4];
    #pragma unroll
    for (int mt = 0; mt < 2; mt++)
        #pragma unroll
        for (int nt = 0; nt < 4; nt++)
            #pragma unroll
            for (int v = 0; v < 4; v++) oacc[mt][nt][v] = 0.f;

    for (int t4 = 0; t4 < 4; t4++) {
        int rwin = topk[np * 4 + t4];
        const float* kb = QKV + (size_t)(n * NWIN + rwin) * 64 * QKC + 256 + mh * 32;
        for (int i = tid; i < 512; i += 64) {
            int r = i >> 3, c = (i & 7) * 4;
            float4 kv = *(const float4*)(kb + (size_t)r * QKC + c);
            ks[r][c + 0] = tf32f(kv.x); ks[r][c + 1] = tf32f(kv.y);
            ks[r][c + 2] = tf32f(kv.z); ks[r][c + 3] = tf32f(kv.w);
            float4 vv = *(const float4*)(kb + (size_t)r * QKC + 256 + c);
            vs[r][c + 0] = tf32f(vv.x); vs[r][c + 1] = tf32f(vv.y);
            vs[r][c + 2] = tf32f(vv.z); vs[r][c + 3] = tf32f(vv.w);
        }
        __syncthreads();

        float sacc[2][8][4];
        #pragma unroll
        for (int mt = 0; mt < 2; mt++)
            #pragma unroll
            for (int nt = 0; nt < 8; nt++)
                #pragma unroll
                for (int v = 0; v < 4; v++) sacc[mt][nt][v] = 0.f;

        #pragma unroll
        for (int kk = 0; kk < 4; kk++) {
            uint32_t bf[8][2];
            #pragma unroll
            for (int nt = 0; nt < 8; nt++) {
                bf[nt][0] = __float_as_uint(ks[nt * 8 + qr][kk * 8 + qc]);
                bf[nt][1] = __float_as_uint(ks[nt * 8 + qr][kk * 8 + qc + 4]);
            }
            #pragma unroll
            for (int mt = 0; mt < 2; mt++)
                #pragma unroll
                for (int nt = 0; nt < 8; nt++) {
                    asm volatile(
                        "mma.sync.aligned.m16n8k8.row.col.f32.tf32.tf32.f32 "
                        "{%0,%1,%2,%3}, {%4,%5,%6,%7}, {%8,%9}, {%0,%1,%2,%3};"
                        : "+f"(sacc[mt][nt][0]), "+f"(sacc[mt][nt][1]),
                          "+f"(sacc[mt][nt][2]), "+f"(sacc[mt][nt][3])
                        : "r"(qf[mt][kk][0]), "r"(qf[mt][kk][1]),
                          "r"(qf[mt][kk][2]), "r"(qf[mt][kk][3]),
                          "r"(bf[nt][0]), "r"(bf[nt][1]));
                }
        }

        float rmax[4] = {-1e30f, -1e30f, -1e30f, -1e30f};
        #pragma unroll
        for (int mt = 0; mt < 2; mt++)
            #pragma unroll
            for (int nt = 0; nt < 8; nt++) {
                rmax[mt * 2 + 0] = fmaxf(rmax[mt * 2 + 0], fmaxf(sacc[mt][nt][0], sacc[mt][nt][1]));
                rmax[mt * 2 + 1] = fmaxf(rmax[mt * 2 + 1], fmaxf(sacc[mt][nt][2], sacc[mt][nt][3]));
            }
        #pragma unroll
        for (int g = 0; g < 4; g++) {
            rmax[g] = fmaxf(rmax[g], __shfl_xor_sync(0xffffffffu, rmax[g], 1));
            rmax[g] = fmaxf(rmax[g], __shfl_xor_sync(0xffffffffu, rmax[g], 2));
        }
        float corr[4], mnew[4];
        #pragma unroll
        for (int g = 0; g < 4; g++) {
            mnew[g] = fmaxf(mrun[g], rmax[g]);
            corr[g] = __expf(mrun[g] - mnew[g]);
            lrun[g] *= corr[g];
            mrun[g] = mnew[g];
        }
        #pragma unroll
        for (int mt = 0; mt < 2; mt++)
            #pragma unroll
            for (int nt = 0; nt < 4; nt++) {
                oacc[mt][nt][0] *= corr[mt * 2 + 0];
                oacc[mt][nt][1] *= corr[mt * 2 + 0];
                oacc[mt][nt][2] *= corr[mt * 2 + 1];
                oacc[mt][nt][3] *= corr[mt * 2 + 1];
            }
        float psum[4] = {0.f, 0.f, 0.f, 0.f};
        #pragma unroll
        for (int mt = 0; mt < 2; mt++) {
            int r0 = warp * 32 + mt * 16 + qr;
            #pragma unroll
            for (int nt = 0; nt < 8; nt++) {
                float p0 = __expf(sacc[mt][nt][0] - mnew[mt * 2 + 0]);
                float p1 = __expf(sacc[mt][nt][1] - mnew[mt * 2 + 0]);
                float p2 = __expf(sacc[mt][nt][2] - mnew[mt * 2 + 1]);
                float p3 = __expf(sacc[mt][nt][3] - mnew[mt * 2 + 1]);
                psum[mt * 2 + 0] += p0 + p1;
                psum[mt * 2 + 1] += p2 + p3;
                float2 w0; w0.x = tf32f(p0); w0.y = tf32f(p1);
                float2 w1; w1.x = tf32f(p2); w1.y = tf32f(p3);
                *(float2*)&ps[r0][nt * 8 + qc * 2]     = w0;
                *(float2*)&ps[r0 + 8][nt * 8 + qc * 2] = w1;
            }
        }
        #pragma unroll
        for (int g = 0; g < 4; g++) {
            psum[g] += __shfl_xor_sync(0xffffffffu, psum[g], 1);
            psum[g] += __shfl_xor_sync(0xffffffffu, psum[g], 2);
            lrun[g] += psum[g];
        }
        __syncwarp();

        #pragma unroll
        for (int kt = 0; kt < 8; kt++) {
            uint32_t af[2][4], bf[4][2];
            #pragma unroll
            for (int mt = 0; mt < 2; mt++) {
                int r = warp * 32 + mt * 16 + qr;
                af[mt][0] = __float_as_uint(ps[r][kt * 8 + qc]);
                af[mt][1] = __float_as_uint(ps[r + 8][kt * 8 + qc]);
                af[mt][2] = __float_as_uint(ps[r][kt * 8 + qc + 4]);
                af[mt][3] = __float_as_uint(ps[r + 8][kt * 8 + qc + 4]);
            }
            #pragma unroll
            for (int nt = 0; nt < 4; nt++) {
                bf[nt][0] = __float_as_uint(vs[kt * 8 + qc][nt * 8 + qr]);
                bf[nt][1] = __float_as_uint(vs[kt * 8 + qc + 4][nt * 8 + qr]);
            }
            #pragma unroll
            for (int mt = 0; mt < 2; mt++)
                #pragma unroll
                for (int nt = 0; nt < 4; nt++) {
                    asm volatile(
                        "mma.sync.aligned.m16n8k8.row.col.f32.tf32.tf32.f32 "
                        "{%0,%1,%2,%3}, {%4,%5,%6,%7}, {%8,%9}, {%0,%1,%2,%3};"
                        : "+f"(oacc[mt][nt][0]), "+f"(oacc[mt][nt][1]),
                          "+f"(oacc[mt][nt][2]), "+f"(oacc[mt][nt][3])
                        : "r"(af[mt][0]), "r"(af[mt][1]), "r"(af[mt][2]), "r"(af[mt][3]),
                          "r"(bf[nt][0]), "r"(bf[nt][1]));
                }
        }
        __syncthreads();
    }

    // ---- finalize: /l, add lepe value (fp32), write bf16 image-order output ----
    float linv[4];
    #pragma unroll
    for (int g = 0; g < 4; g++) linv[g] = 1.0f / lrun[g];

    int jj = p / 7, ii = p % 7;
    #pragma unroll
    for (int mt = 0; mt < 2; mt++) {
        #pragma unroll
        for (int half = 0; half < 2; half++) {
            int q = warp * 32 + mt * 16 + qr + half * 8;
            int y = jj * 8 + (q >> 3), x = ii * 8 + (q & 7);
            size_t base = ((size_t)(n * HWDIM + y) * HWDIM + x) * CDIM + mh * 32;
            const float* lrow = L + base;
            __nv_bfloat16* orow = O + base;
            float li = linv[mt * 2 + half];
            #pragma unroll
            for (int nt = 0; nt < 4; nt++) {
                float2 lv = *(const float2*)(lrow + nt * 8 + qc * 2);
                float a0 = oacc[mt][nt][half * 2 + 0] * li + lv.x;
                float a1 = oacc[mt][nt][half * 2 + 1] * li + lv.y;
                __nv_bfloat162 ov = __floats2bfloat162_rn(a0, a1);
                *(__nv_bfloat162*)(orow + nt * 8 + qc * 2) = ov;
            }
        }
    }
}

// ---------------- host launch ----------------
extern "C" void kernel_launch(void* const* d_in, const int* in_sizes, int n_in,
                              void* d_out, int out_size) {
    const float* x      = (const float*)d_in[0];
    const float* ln1_g  = (const float*)d_in[1];
    const float* ln1_b  = (const float*)d_in[2];
    const float* qkv_w  = (const float*)d_in[3];
    const float* qkv_b  = (const float*)d_in[4];
    const float* lepe_w = (const float*)d_in[5];
    const float* lepe_b = (const float*)d_in[6];
    const float* wo_w   = (const float*)d_in[7];
    const float* wo_b   = (const float*)d_in[8];
    const float* ln2_g  = (const float*)d_in[9];
    const float* ln2_b  = (const float*)d_in[10];
    const float* mlp_w1 = (const float*)d_in[11];
    const float* mlp_b1 = (const float*)d_in[12];
    const float* mlp_w2 = (const float*)d_in[13];
    const float* mlp_b2 = (const float*)d_in[14];
    float* out = (float*)d_out;

    float *tmp, *qkv, *x1, *hid, *qw, *kw;
    int* tk;
    __nv_bfloat16* wbf;
    cudaGetSymbolAddress((void**)&tmp, g_tmp256);
    cudaGetSymbolAddress((void**)&qkv, g_qkv);
    cudaGetSymbolAddress((void**)&x1,  g_x1);
    cudaGetSymbolAddress((void**)&hid, g_hid);
    cudaGetSymbolAddress((void**)&qw,  g_qwin);
    cudaGetSymbolAddress((void**)&kw,  g_kwin);
    cudaGetSymbolAddress((void**)&tk,  g_topk);
    cudaGetSymbolAddress((void**)&wbf, g_wbf);
    __nv_bfloat16* tmpb = (__nv_bfloat16*)tmp;
    __nv_bfloat16* hidb = (__nv_bfloat16*)hid;

    // 1. transpose + bf16-convert ALL weights (single launch)
    wtrans_all_kernel<<<768, 256>>>(qkv_w, wo_w, mlp_w1, mlp_w2, wbf);
    // 2. LN1 with window permute -> bf16
    ln_kernel<true><<<TOK / 8, 256>>>(x, ln1_g, ln1_b, tmpb);
    // 3. qkv GEMM (bf16 A, fused window means)
    tgemm_kernel<0, 1, 1><<<dim3(QKC / 128, TOK / 128), 256>>>(
        tmpb, wbf + WT_QKV, qkv_b, nullptr, qkv, qw, kw, TOK, QKC, CDIM);
    // 4. router + top-4
    router_kernel<<<NPALL, 256>>>(qw, kw, tk);
    // 5. lepe depthwise conv -> tmp (fp32, image order, first writer)
    lepe_kernel<<<dim3(NPALL, 4), 256>>>(qkv, lepe_w, lepe_b, tmp);
    // 6. gathered attention (+lepe from tmp) -> bf16 hid
    attn_kernel<<<dim3(NPALL, 8), 64>>>(qkv, tk, tmp, hidb);
    // 7. wo GEMM (bf16 A) + residual -> x1
    tgemm_kernel<2, 1, 0><<<dim3(CDIM / 128, TOK / 128), 256>>>(
        hidb, wbf + WT_WO, wo_b, x, x1, nullptr, nullptr, TOK, CDIM, CDIM);
    // 8. LN2 -> bf16
    ln_kernel<false><<<TOK / 8, 256>>>(x1, ln2_g, ln2_b, tmpb);
    // 9. MLP1 + GELU -> bf16 hid
    tgemm_kernel<1, 1, 0><<<dim3(HIDC / 128, TOK / 128), 256>>>(
        tmpb, wbf + WT_W1, mlp_b1, nullptr, hidb, nullptr, nullptr, TOK, HIDC, CDIM);
    // 10. MLP2 (bf16 A) + residual -> out
    tgemm_kernel<2, 1, 0><<<dim3(CDIM / 128, TOK / 128), 256>>>(
        hidb, wbf + WT_W2, mlp_b2, x1, out, nullptr, nullptr, TOK, CDIM, HIDC);
}